// round 12
// baseline (speedup 1.0000x reference)
#include <cuda_runtime.h>
#include <cuda_bf16.h>
#include <cstdint>

// Problem constants
#define NN 200000
#define MM 200
#define DM 100
#define DE 172
#define EE 8192
#define KK 10
#define TAU 2.0f

#define E2 (2*EE)     // 16384
#define E3 (3*EE)     // 24576

// ----------------- persistent scratch (zero-initialized at load) -----------------
__device__ float g_merged12[E2 * MM];
__device__ float g_msgs[E2 * DM];
__device__ float g_gh[E2 * 600];
__device__ float g_gxp[E2 * 800];      // [rx zx nx | prop] fused
__device__ float g_delta_s[(long)NN * MM];
__device__ float g_delta_g[(long)NN * MM];
__device__ int   g_last_s[NN];
__device__ int   g_last_g[NN];
__device__ float g_A3[E3 * 400];
__device__ float g_merged3[E3 * MM];
__device__ float g_proj[E3 * DM];
__device__ float g_ef[EE * DE];

// tf32-rounded weight copies (concatenated)
#define OFF_WMERGE 0
#define OFF_WMSG   80000
#define OFF_WHS    137200
#define OFF_WHG    257200
#define OFF_WS     377200
#define OFF_WG     397200
#define WCVT_TOTAL 417200
__device__ float g_wcvt[WCVT_TOTAL];
__device__ float g_wxp[2 * 100 * 800];   // [Wx|Wp] per side, tf32-rounded
__device__ float g_bxp[2 * 800];         // [bg|0] per side

__device__ __forceinline__ uint32_t f2tf32(float f) {
    uint32_t r;
    asm("cvt.rna.tf32.f32 %0, %1;" : "=r"(r) : "f"(f));
    return r;
}
__device__ __forceinline__ float roundtf(float f) { return __uint_as_float(f2tf32(f)); }

// ----------------- GEMM machinery -----------------
__device__ __forceinline__ void mma_tf32(float* c, const uint32_t* a, const uint32_t* b) {
    asm volatile("mma.sync.aligned.m16n8k8.row.col.f32.tf32.tf32.f32 "
                 "{%0,%1,%2,%3}, {%4,%5,%6,%7}, {%8,%9}, {%0,%1,%2,%3};"
                 : "+f"(c[0]), "+f"(c[1]), "+f"(c[2]), "+f"(c[3])
                 : "r"(a[0]), "r"(a[1]), "r"(a[2]), "r"(a[3]),
                   "r"(b[0]), "r"(b[1]));
}
__device__ __forceinline__ void cp_async16(uint32_t dst, const void* src, int sz) {
    asm volatile("cp.async.cg.shared.global [%0], [%1], 16, %2;"
                 :: "r"(dst), "l"(src), "r"(sz) : "memory");
}
__device__ __forceinline__ void cp_commit() { asm volatile("cp.async.commit_group;" ::: "memory"); }
template<int N> __device__ __forceinline__ void cp_wait() {
    asm volatile("cp.async.wait_group %0;" :: "n"(N) : "memory");
}
__device__ __forceinline__ uint32_t smem_u32(const void* p) {
    uint32_t a;
    asm("{ .reg .u64 t; cvta.to.shared.u64 t, %1; cvt.u32.u64 %0, t; }" : "=r"(a) : "l"(p));
    return a;
}

#define ASTRIDE 40
#define AWORDS (128*ASTRIDE)               // 5120
#define BSTRIDE 72
#define BWORDS (32*BSTRIDE)                // 2304
#define STAGE_WORDS (AWORDS + BWORDS)      // 7424
#define NSTAGE 3
#define SMEM_BYTES (NSTAGE*STAGE_WORDS*4)  // 89088

struct GemmP {
    const float* A; int lda, Kdim;
    const float* P0; const float* P1;
    const int* i0; const int* i1;
    const float* B0; const float* B1;
    const float* bias0; const float* bias1; int rowSwitch;
    float* C; int Ndim, act, roundOut, gx;
};

// MODE 0: A[r][k] = A[r*lda + k]
// MODE 1: A[r][k] = k<200 ? P0[n][k] : P1[n][k-200],  n = r<E?i0[r]:i1[r-E]
// MODE 3: A[r][k] = k<200 ? A[r][k] : k<400 ? A[r_other][k-200] : g_ef[e][k-400]
// MODE 4: A[r][k] = (r<E ? P0[i0[r]] : P1[i1[r-E]])[k]
// B rows K-permuted per 8-slab (k -> (k&1 ? k/2+4 : k/2)) so A frags use LDS.64.
template<int MODE, bool CVTA>
__device__ void gemm_body(const GemmP& P, int bx, int by, float* smf)
{
    uint32_t smemBase = smem_u32(smf);
    int blockRow = by * 128;
    int blockCol = bx * 64;
    bool firstSide = blockRow < P.rowSwitch;
    const float* B    = firstSide ? P.B0 : P.B1;
    const float* bias = firstSide ? P.bias0 : P.bias1;
    int Kdim = P.Kdim, Ndim = P.Ndim;

    int tid = threadIdx.x, lane = tid & 31, warp = tid >> 5;
    int wm = (warp & 3) * 32, wn = (warp >> 2) * 32;
    int g = lane >> 2, tg = lane & 3;

    const float* rp0[4]; const float* rp1[4]; const float* rp2[4];
    #pragma unroll
    for (int i = 0; i < 4; i++) {
        int r = blockRow + ((tid + i*256) >> 3);
        if (MODE == 0) {
            rp0[i] = P.A + (long)r * P.lda;
        } else if (MODE == 1) {
            int node = (r < EE) ? P.i0[r] : P.i1[r - EE];
            rp0[i] = P.P0 + (long)node * MM;
            rp1[i] = P.P1 + (long)node * MM;
        } else if (MODE == 3) {
            int e  = (r < EE) ? r : r - EE;
            int r2 = (r < EE) ? (r + EE) : (r - EE);
            rp0[i] = P.A + (long)r * MM;
            rp1[i] = P.A + (long)r2 * MM;
            rp2[i] = g_ef + (long)e * DE;
        } else {
            int node = (r < EE) ? P.i0[r] : P.i1[r - EE];
            rp0[i] = ((r < EE) ? P.P0 : P.P1) + (long)node * MM;
        }
    }

    auto issue = [&](int t) {
        int s = t % NSTAGE;
        uint32_t aB = smemBase + (uint32_t)(s * STAGE_WORDS) * 4u;
        uint32_t bB = aB + AWORDS * 4u;
        int k0 = t * 32;
        #pragma unroll
        for (int i = 0; i < 4; i++) {
            int idx = tid + i*256;
            int rl = idx >> 3, q = idx & 7;
            int k = k0 + q * 4;
            uint32_t dst = aB + (uint32_t)(rl * ASTRIDE + q * 4) * 4u;
            const float* src; int sz = 16;
            if (MODE == 0) {
                src = rp0[i] + k; if (k >= Kdim) sz = 0;
            } else if (MODE == 1) {
                src = (k < MM) ? rp0[i] + k : rp1[i] + k - MM;
            } else if (MODE == 3) {
                if (k < MM)        src = rp0[i] + k;
                else if (k < 2*MM) src = rp1[i] + k - MM;
                else { src = rp2[i] + k - 2*MM; if (k >= 2*MM + DE) sz = 0; }
            } else {
                src = rp0[i] + k; if (k >= MM) sz = 0;
            }
            cp_async16(dst, src, sz);
        }
        #pragma unroll
        for (int i = 0; i < 2; i++) {
            int idx = tid + i*256;
            int kr = idx >> 4, n4 = (idx & 15) * 4;
            int k = k0 + kr, n = blockCol + n4;
            int l = kr & 7;
            int phys = (kr & ~7) + ((l & 1) ? (l >> 1) + 4 : (l >> 1));
            uint32_t dst = bB + (uint32_t)(phys * BSTRIDE + n4) * 4u;
            const float* src = B + (long)k * Ndim + n;
            int sz = (k < Kdim && n < Ndim) ? 16 : 0;
            cp_async16(dst, src, sz);
        }
    };

    float acc[2][4][4];
    #pragma unroll
    for (int i = 0; i < 2; i++)
        #pragma unroll
        for (int j = 0; j < 4; j++)
            #pragma unroll
            for (int q = 0; q < 4; q++) acc[i][j][q] = 0.0f;

    int nT = (Kdim + 31) / 32;
    issue(0); cp_commit();
    if (nT > 1) issue(1);
    cp_commit();

    uint32_t afr[2][2][4], bfr[2][4][2];
    for (int t = 0; t < nT; t++) {
        cp_wait<1>();
        __syncthreads();
        if (t + 2 < nT) issue(t + 2);
        cp_commit();

        const uint32_t* Asm = (const uint32_t*)smf + (t % NSTAGE) * STAGE_WORDS;
        const uint32_t* Bsm = Asm + AWORDS;

        auto loadFrag = [&](int ks, int bf) {
            #pragma unroll
            for (int mt = 0; mt < 2; mt++) {
                int mr = wm + mt*16 + g;
                uint2 v0 = *(const uint2*)&Asm[(mr    ) * ASTRIDE + ks*8 + 2*tg];
                uint2 v1 = *(const uint2*)&Asm[(mr + 8) * ASTRIDE + ks*8 + 2*tg];
                if (CVTA) {
                    afr[bf][mt][0] = f2tf32(__uint_as_float(v0.x));
                    afr[bf][mt][2] = f2tf32(__uint_as_float(v0.y));
                    afr[bf][mt][1] = f2tf32(__uint_as_float(v1.x));
                    afr[bf][mt][3] = f2tf32(__uint_as_float(v1.y));
                } else {
                    afr[bf][mt][0] = v0.x; afr[bf][mt][2] = v0.y;
                    afr[bf][mt][1] = v1.x; afr[bf][mt][3] = v1.y;
                }
            }
            #pragma unroll
            for (int nt = 0; nt < 4; nt++) {
                int nc = wn + nt*8 + g;
                bfr[bf][nt][0] = Bsm[(ks*8 + tg) * BSTRIDE + nc];
                bfr[bf][nt][1] = Bsm[(ks*8 + tg + 4) * BSTRIDE + nc];
            }
        };

        loadFrag(0, 0);
        #pragma unroll
        for (int ks = 0; ks < 4; ks++) {
            int cur = ks & 1;
            if (ks < 3) loadFrag(ks + 1, cur ^ 1);
            #pragma unroll
            for (int mt = 0; mt < 2; mt++)
                #pragma unroll
                for (int nt = 0; nt < 4; nt++)
                    mma_tf32(acc[mt][nt], afr[cur][mt], bfr[cur][nt]);
        }
    }

    #pragma unroll
    for (int mt = 0; mt < 2; mt++) {
        #pragma unroll
        for (int nt = 0; nt < 4; nt++) {
            int r0 = blockRow + wm + mt*16 + g;
            int c0 = blockCol + wn + nt*8 + tg*2;
            float bv0 = 0.0f, bv1 = 0.0f;
            if (bias) {
                if (c0     < Ndim) bv0 = bias[c0];
                if (c0 + 1 < Ndim) bv1 = bias[c0 + 1];
            }
            #pragma unroll
            for (int q = 0; q < 4; q++) {
                int r = r0 + (q >> 1) * 8;
                int c = c0 + (q & 1);
                if (c >= Ndim) continue;
                float v = acc[mt][nt][q] + ((q & 1) ? bv1 : bv0);
                if (P.act == 1) v = tanhf(v);
                else if (P.act == 2) v = fmaxf(v, 0.0f);
                else if (P.act == 3 && c >= 600) v = tanhf(v);
                if (P.roundOut) v = roundtf(v);
                P.C[(long)r * Ndim + c] = v;
            }
        }
    }
}

template<int MODE, bool CVTA>
__global__ __launch_bounds__(256) void gemm_tc(GemmP P)
{
    extern __shared__ float smf[];
    gemm_body<MODE, CVTA>(P, blockIdx.x, blockIdx.y, smf);
}

// ----------------- combo1: cvt_weights + cvt_xp + prep_ef -----------------
#define NB_W  ((WCVT_TOTAL + 255) / 256)   // 1630
#define NB_XP ((161600 + 255) / 256)       // 632
#define NB_EF (EE / 8)                     // 1024
__global__ void combo1_kernel(const float* __restrict__ wm, const float* __restrict__ wmsg,
                              const float* __restrict__ whs, const float* __restrict__ whg,
                              const float* __restrict__ ws,  const float* __restrict__ wg,
                              const float* __restrict__ wxs, const float* __restrict__ wps,
                              const float* __restrict__ wxg, const float* __restrict__ wpg,
                              const float* __restrict__ bgs, const float* __restrict__ bgg,
                              const float* __restrict__ edge_feats, const int* __restrict__ eidx)
{
    int b = blockIdx.x;
    if (b < NB_W) {
        int i = b * 256 + threadIdx.x;
        if (i >= WCVT_TOTAL) return;
        const float* s; int o;
        if      (i < OFF_WMSG) { s = wm;   o = i - OFF_WMERGE; }
        else if (i < OFF_WHS)  { s = wmsg; o = i - OFF_WMSG; }
        else if (i < OFF_WHG)  { s = whs;  o = i - OFF_WHS; }
        else if (i < OFF_WS)   { s = whg;  o = i - OFF_WHG; }
        else if (i < OFF_WG)   { s = ws;   o = i - OFF_WS; }
        else                   { s = wg;   o = i - OFF_WG; }
        g_wcvt[i] = roundtf(s[o]);
    } else if (b < NB_W + NB_XP) {
        int i = (b - NB_W) * 256 + threadIdx.x;
        if (i < 160000) {
            int side = i / 80000, rem = i % 80000;
            int k = rem / 800, n = rem % 800;
            const float* wx = side ? wxg : wxs;
            const float* wp = side ? wpg : wps;
            float v = (n < 600) ? wx[k * 600 + n] : wp[k * 200 + (n - 600)];
            g_wxp[i] = roundtf(v);
        } else if (i < 161600) {
            int j = i - 160000;
            int side = j / 800, n = j % 800;
            const float* bg = side ? bgg : bgs;
            g_bxp[j] = (n < 600) ? bg[n] : 0.0f;
        }
    } else {
        int e = (b - NB_W - NB_XP) * 8 + (threadIdx.x >> 5);
        int lane = threadIdx.x & 31;
        if (e >= EE) return;
        const float4* s = (const float4*)(edge_feats + (long)eidx[e] * DE);
        float4* o = (float4*)(g_ef + (long)e * DE);
        #pragma unroll
        for (int c = lane; c < DE/4; c += 32) {
            float4 v = s[c];
            o[c] = make_float4(roundtf(v.x), roundtf(v.y), roundtf(v.z), roundtf(v.w));
        }
    }
}

// ----------------- combo2: merge12 GEMM + gh GEMM + zero_init + last_occ -----------
#define NTASKS (2*EE*(KK+1))   // 180224
#define G1 (4 * (E2/128))      // 512   merge12
#define G2 (10 * (E2/128))     // 1280  gh
#define GZ (NTASKS / 8)        // 22528 zero_init
#define GL 32                  // last_occ
__global__ __launch_bounds__(256) void combo2_kernel(
    GemmP P1, GemmP P2,
    const int* __restrict__ src, const int* __restrict__ dst,
    const int* __restrict__ neighbors)
{
    extern __shared__ float smf[];
    int b = blockIdx.x;
    if (b < G1) {
        gemm_body<1, true>(P1, b % 4, b / 4, smf);
    } else if (b < G1 + G2) {
        int vb = b - G1;
        gemm_body<4, true>(P2, vb % 10, vb / 10, smf);
    } else if (b < G1 + G2 + GZ) {
        int t = (b - G1 - G2) * 8 + (threadIdx.x >> 5);
        int lane = threadIdx.x & 31;
        if (t >= NTASKS) return;
        float* delta;
        int node;
        if (t < EE) {
            node = src[t]; delta = g_delta_s;
            if (lane == 0) g_last_s[node] = -1;
        } else if (t < E2) {
            node = dst[t - EE]; delta = g_delta_g;
            if (lane == 0) g_last_g[node] = -1;
        } else if (t < E2 + EE*KK) {
            int q = t - E2;
            node = neighbors[(long)src[q / KK] * KK + (q % KK)];
            delta = g_delta_s;
        } else {
            int q = t - E2 - EE*KK;
            node = neighbors[(long)dst[q / KK] * KK + (q % KK)];
            delta = g_delta_g;
        }
        float4* p = (float4*)(delta + (long)node * MM);
        float4 z = make_float4(0.f, 0.f, 0.f, 0.f);
        #pragma unroll
        for (int c = lane; c < MM/4; c += 32) p[c] = z;
    } else {
        int e = (b - G1 - G2 - GZ) * 256 + threadIdx.x;
        if (e >= EE) return;
        atomicMax(&g_last_s[src[e]], e);
        atomicMax(&g_last_g[dst[e]], e);
    }
}

// ----------------- prep_A3 -----------------
__global__ void prep_A3_kernel(const float* __restrict__ mem_s, const float* __restrict__ mem_g,
                               const int* __restrict__ src, const int* __restrict__ dst,
                               const int* __restrict__ neg)
{
    int r = blockIdx.x * 8 + (threadIdx.x >> 5);
    int lane = threadIdx.x & 31;
    if (r >= E3) return;
    int idx = (r < EE) ? src[r] : ((r < E2) ? dst[r - EE] : neg[r - E2]);
    const float4* ps = (const float4*)(mem_s + (long)idx * MM);
    const float4* pg = (const float4*)(mem_g + (long)idx * MM);
    const float4* ds = (const float4*)(g_delta_s + (long)idx * MM);
    const float4* dg = (const float4*)(g_delta_g + (long)idx * MM);
    float4* o = (float4*)(g_A3 + (long)r * 400);
    #pragma unroll
    for (int c = lane; c < 100; c += 32) {
        float4 a = (c < 50) ? ps[c] : pg[c - 50];
        float4 d = (c < 50) ? ds[c] : dg[c - 50];
        o[c] = make_float4(roundtf(a.x + d.x), roundtf(a.y + d.y),
                           roundtf(a.z + d.z), roundtf(a.w + d.w));
    }
}

// ----------------- GRU + neighbor-propagation scatter -----------------
__device__ __forceinline__ float sigmoidf_(float x) { return 1.0f / (1.0f + expf(-x)); }

__global__ void gru_scatter_kernel(const float* __restrict__ mem_s, const float* __restrict__ mem_g,
                                   const int* __restrict__ src, const int* __restrict__ dst,
                                   const int* __restrict__ neighbors,
                                   const float* __restrict__ times,
                                   const float* __restrict__ lu_s, const float* __restrict__ lu_g)
{
    int row = blockIdx.x;
    bool sideS = (row < EE);
    int e = sideS ? row : (row - EE);
    int node = sideS ? src[e] : dst[e];
    int last = sideS ? g_last_s[node] : g_last_g[node];
    if (last != e) return;
    int m = threadIdx.x;
    if (m >= MM) return;

    float* delta = sideS ? g_delta_s : g_delta_g;
    const float* lu = sideS ? lu_s : lu_g;

    float h = (sideS ? mem_s : mem_g)[(long)node * MM + m];
    long gb = (long)row * 800;
    float rx = g_gxp[gb + m], zx = g_gxp[gb + MM + m], nx = g_gxp[gb + 2*MM + m];
    float p  = g_gxp[gb + 3*MM + m];
    long hb = (long)row * 600;
    float rh = g_gh[hb + m], zh = g_gh[hb + MM + m], nh = g_gh[hb + 2*MM + m];
    float r = sigmoidf_(rx + rh);
    float z = sigmoidf_(zx + zh);
    float n = tanhf(nx + r * nh);
    float new_h = (1.0f - z) * n + z * h;
    atomicAdd(&delta[(long)node * MM + m], new_h - h);

    float t = times[e];
    #pragma unroll
    for (int k = 0; k < KK; k++) {
        int nb = neighbors[(long)node * KK + k];
        float dt = t - lu[nb];
        dt = fminf(fmaxf(dt, 0.0f), 50.0f);
        float decay = expf(-dt * (1.0f / TAU));
        atomicAdd(&delta[(long)nb * MM + m], decay * p);
    }
}

// ----------------- final dot + sigmoid -----------------
__global__ void score_kernel(float* __restrict__ out)
{
    int gw = (blockIdx.x * blockDim.x + threadIdx.x) >> 5;
    int lane = threadIdx.x & 31;
    if (gw >= E2) return;
    int e = (gw < EE) ? gw : (gw - EE);
    const float* u = g_proj + (long)e * DM;
    const float* v = g_proj + (long)((gw < EE) ? (EE + e) : (E2 + e)) * DM;
    float s = 0.0f;
    for (int c = lane; c < DM; c += 32) s += u[c] * v[c];
    #pragma unroll
    for (int off = 16; off > 0; off >>= 1) s += __shfl_down_sync(0xffffffffu, s, off);
    if (lane == 0) out[gw] = 1.0f / (1.0f + expf(-s));
}

// ----------------- launch -----------------
extern "C" void kernel_launch(void* const* d_in, const int* in_sizes, int n_in,
                              void* d_out, int out_size)
{
    const float* mem_s   = (const float*)d_in[0];
    const float* mem_g   = (const float*)d_in[1];
    const float* lu_s    = (const float*)d_in[2];
    const float* lu_g    = (const float*)d_in[3];
    const float* efeats  = (const float*)d_in[4];
    const float* etimes  = (const float*)d_in[5];
    const int*   src     = (const int*)d_in[6];
    const int*   dst     = (const int*)d_in[7];
    const int*   neg     = (const int*)d_in[8];
    const int*   eidx    = (const int*)d_in[9];
    const int*   nbrs    = (const int*)d_in[10];
    const float* W_merge = (const float*)d_in[11];
    const float* b_merge = (const float*)d_in[12];
    const float* W_msg   = (const float*)d_in[13];
    const float* b_msg   = (const float*)d_in[14];
    const float* Wx_s    = (const float*)d_in[15];
    const float* Wh_s    = (const float*)d_in[16];
    const float* bg_s    = (const float*)d_in[17];
    const float* Wx_g    = (const float*)d_in[18];
    const float* Wh_g    = (const float*)d_in[19];
    const float* bg_g    = (const float*)d_in[20];
    const float* Wp_s    = (const float*)d_in[21];
    const float* Wp_g    = (const float*)d_in[22];
    const float* W_s     = (const float*)d_in[23];
    const float* W_g     = (const float*)d_in[24];
    float* out = (float*)d_out;

    float *pMerged12, *pMsgs, *pGh, *pGxp, *pA3, *pMerged3, *pProj, *pW, *pWxp, *pBxp;
    cudaGetSymbolAddress((void**)&pMerged12, g_merged12);
    cudaGetSymbolAddress((void**)&pMsgs,     g_msgs);
    cudaGetSymbolAddress((void**)&pGh,       g_gh);
    cudaGetSymbolAddress((void**)&pGxp,      g_gxp);
    cudaGetSymbolAddress((void**)&pA3,       g_A3);
    cudaGetSymbolAddress((void**)&pMerged3,  g_merged3);
    cudaGetSymbolAddress((void**)&pProj,     g_proj);
    cudaGetSymbolAddress((void**)&pW,        g_wcvt);
    cudaGetSymbolAddress((void**)&pWxp,      g_wxp);
    cudaGetSymbolAddress((void**)&pBxp,      g_bxp);

    cudaFuncSetAttribute(gemm_tc<0,false>, cudaFuncAttributeMaxDynamicSharedMemorySize, SMEM_BYTES);
    cudaFuncSetAttribute(gemm_tc<3,false>, cudaFuncAttributeMaxDynamicSharedMemorySize, SMEM_BYTES);
    cudaFuncSetAttribute(combo2_kernel,    cudaFuncAttributeMaxDynamicSharedMemorySize, SMEM_BYTES);

    const int BIG = 1 << 30;
    const float* cWm   = pW + OFF_WMERGE;
    const float* cWmsg = pW + OFF_WMSG;
    const float* cWhs  = pW + OFF_WHS;
    const float* cWhg  = pW + OFF_WHG;
    const float* cWs   = pW + OFF_WS;
    const float* cWg   = pW + OFF_WG;

    // L1: all weight/ef conversions in one launch
    combo1_kernel<<<NB_W + NB_XP + NB_EF, 256>>>(
        W_merge, W_msg, Wh_s, Wh_g, W_s, W_g,
        Wx_s, Wp_s, Wx_g, Wp_g, bg_s, bg_g, efeats, eidx);

    // L2: merge12 GEMM + gh GEMM + zero_init + last_occ (mutually independent)
    GemmP Pm12 = { nullptr, 0, 400, mem_s, mem_g, src, dst,
                   cWm, cWm, b_merge, b_merge, BIG, pMerged12, MM, 1, 1, 4 };
    GemmP Pgh  = { nullptr, 0, 200, mem_s, mem_g, src, dst,
                   cWhs, cWhg, nullptr, nullptr, EE, pGh, 600, 0, 0, 10 };
    combo2_kernel<<<G1 + G2 + GZ + GL, 256, SMEM_BYTES>>>(Pm12, Pgh, src, dst, nbrs);

    // L3: msgs = round(relu(concat @ Wmsg + b))   [E2 x 572]x[572 x 100]
    GemmP Pmsg = { pMerged12, 0, 572, nullptr, nullptr, nullptr, nullptr,
                   cWmsg, cWmsg, b_msg, b_msg, BIG, pMsgs, DM, 2, 1, 2 };
    gemm_tc<3,false><<<dim3(2, E2/128), 256, SMEM_BYTES>>>(Pmsg);

    // L4: gxp = msgs @ [Wx|Wp] + [bg|0]; tanh cols>=600   [E2 x 100]x[100 x 800]
    GemmP Pgxp = { pMsgs, DM, DM, nullptr, nullptr, nullptr, nullptr,
                   pWxp, pWxp + 80000, pBxp, pBxp + 800, EE, pGxp, 800, 3, 0, 13 };
    gemm_tc<0,false><<<dim3(13, E2/128), 256, SMEM_BYTES>>>(Pgxp);

    // L5: GRU elementwise + scatter
    gru_scatter_kernel<<<E2, 256>>>(mem_s, mem_g, src, dst, nbrs, etimes, lu_s, lu_g);

    // L6: A3 = round(mem+delta)
    prep_A3_kernel<<<E3/8, 256>>>(mem_s, mem_g, src, dst, neg);

    // L7: merged3 = round(tanh(A3 @ Wm + b))   [E3 x 400]x[400 x 200]
    GemmP Pm3 = { pA3, 400, 400, nullptr, nullptr, nullptr, nullptr,
                  cWm, cWm, b_merge, b_merge, BIG, pMerged3, MM, 1, 1, 4 };
    gemm_tc<0,false><<<dim3(4, E3/128), 256, SMEM_BYTES>>>(Pm3);

    // L8: proj = merged3 @ (W_s | W_g)   [E3 x 200]x[200 x 100]
    GemmP Ppr = { pMerged3, MM, MM, nullptr, nullptr, nullptr, nullptr,
                  cWs, cWg, nullptr, nullptr, EE, pProj, DM, 0, 0, 2 };
    gemm_tc<0,false><<<dim3(2, E3/128), 256, SMEM_BYTES>>>(Ppr);

    // L9: score
    score_kernel<<<(E2 * 32 + 255) / 256, 256>>>(out);
}

// round 13
// speedup vs baseline: 1.1414x; 1.1414x over previous
#include <cuda_runtime.h>
#include <cuda_bf16.h>
#include <cstdint>

// Problem constants
#define NN 200000
#define MM 200
#define DM 100
#define DE 172
#define EE 8192
#define KK 10
#define TAU 2.0f

#define E2 (2*EE)     // 16384
#define E3 (3*EE)     // 24576

// ----------------- persistent scratch (zero-initialized at load) -----------------
__device__ float g_merged12[E2 * MM];
__device__ float g_msgs[E2 * DM];
__device__ float g_gh[E2 * 600];
__device__ float g_gxp[E2 * 800];      // [rx zx nx | prop] fused
__device__ float g_delta_s[(long)NN * MM];
__device__ float g_delta_g[(long)NN * MM];
__device__ int   g_last_s[NN];
__device__ int   g_last_g[NN];
__device__ float g_A3[E3 * 400];
__device__ float g_merged3[E3 * MM];
__device__ float g_proj[E3 * DM];
__device__ float g_ef[EE * DE];

// tf32-rounded weight copies (concatenated)
#define OFF_WMERGE 0
#define OFF_WMSG   80000
#define OFF_WHS    137200
#define OFF_WHG    257200
#define OFF_WS     377200
#define OFF_WG     397200
#define WCVT_TOTAL 417200
__device__ float g_wcvt[WCVT_TOTAL];
__device__ float g_wxp[2 * 100 * 800];   // [Wx|Wp] per side, tf32-rounded
__device__ float g_bxp[2 * 800];         // [bg|0] per side

__device__ __forceinline__ uint32_t f2tf32(float f) {
    uint32_t r;
    asm("cvt.rna.tf32.f32 %0, %1;" : "=r"(r) : "f"(f));
    return r;
}
__device__ __forceinline__ float roundtf(float f) { return __uint_as_float(f2tf32(f)); }

// ----------------- combo1: cvt_weights + cvt_xp + prep_ef -----------------
#define NB_W  ((WCVT_TOTAL + 255) / 256)   // 1630
#define NB_XP ((161600 + 255) / 256)       // 632
#define NB_EF (EE / 8)                     // 1024
__global__ void combo1_kernel(const float* __restrict__ wm, const float* __restrict__ wmsg,
                              const float* __restrict__ whs, const float* __restrict__ whg,
                              const float* __restrict__ ws,  const float* __restrict__ wg,
                              const float* __restrict__ wxs, const float* __restrict__ wps,
                              const float* __restrict__ wxg, const float* __restrict__ wpg,
                              const float* __restrict__ bgs, const float* __restrict__ bgg,
                              const float* __restrict__ edge_feats, const int* __restrict__ eidx)
{
    int b = blockIdx.x;
    if (b < NB_W) {
        int i = b * 256 + threadIdx.x;
        if (i >= WCVT_TOTAL) return;
        const float* s; int o;
        if      (i < OFF_WMSG) { s = wm;   o = i - OFF_WMERGE; }
        else if (i < OFF_WHS)  { s = wmsg; o = i - OFF_WMSG; }
        else if (i < OFF_WHG)  { s = whs;  o = i - OFF_WHS; }
        else if (i < OFF_WS)   { s = whg;  o = i - OFF_WHG; }
        else if (i < OFF_WG)   { s = ws;   o = i - OFF_WS; }
        else                   { s = wg;   o = i - OFF_WG; }
        g_wcvt[i] = roundtf(s[o]);
    } else if (b < NB_W + NB_XP) {
        int i = (b - NB_W) * 256 + threadIdx.x;
        if (i < 160000) {
            int side = i / 80000, rem = i % 80000;
            int k = rem / 800, n = rem % 800;
            const float* wx = side ? wxg : wxs;
            const float* wp = side ? wpg : wps;
            float v = (n < 600) ? wx[k * 600 + n] : wp[k * 200 + (n - 600)];
            g_wxp[i] = roundtf(v);
        } else if (i < 161600) {
            int j = i - 160000;
            int side = j / 800, n = j % 800;
            const float* bg = side ? bgg : bgs;
            g_bxp[j] = (n < 600) ? bg[n] : 0.0f;
        }
    } else {
        int e = (b - NB_W - NB_XP) * 8 + (threadIdx.x >> 5);
        int lane = threadIdx.x & 31;
        if (e >= EE) return;
        const float4* s = (const float4*)(edge_feats + (long)eidx[e] * DE);
        float4* o = (float4*)(g_ef + (long)e * DE);
        #pragma unroll
        for (int c = lane; c < DE/4; c += 32) {
            float4 v = s[c];
            o[c] = make_float4(roundtf(v.x), roundtf(v.y), roundtf(v.z), roundtf(v.w));
        }
    }
}

// ----------------- zero only the rows that will be READ ({src,dst,neg} x both sides) --
// Scatter-adds land on arbitrary neighbor rows, but prep_A3 only reads delta at
// {src,dst,neg}; unread rows may hold stale garbage across graph replays without
// affecting output. 6E tasks instead of 2E(K+1).
#define NZTASKS (6*EE)   // 49152
__global__ void zero_init_kernel(const int* __restrict__ src, const int* __restrict__ dst,
                                 const int* __restrict__ neg)
{
    int t = blockIdx.x * 8 + (threadIdx.x >> 5);
    int lane = threadIdx.x & 31;
    if (t >= NZTASKS) return;
    int q = (t < E3) ? t : (t - E3);
    float* delta = (t < E3) ? g_delta_s : g_delta_g;
    int node;
    if (q < EE) {
        node = src[q];
        if (t < E3 && lane == 0) g_last_s[node] = -1;
    } else if (q < E2) {
        node = dst[q - EE];
        if (t < E3 && lane == 0) g_last_g[node] = -1;
    } else {
        node = neg[q - E2];
    }
    float4* p = (float4*)(delta + (long)node * MM);
    float4 z = make_float4(0.f, 0.f, 0.f, 0.f);
    #pragma unroll
    for (int c = lane; c < MM/4; c += 32) p[c] = z;
}

__global__ void last_occ_kernel(const int* __restrict__ src, const int* __restrict__ dst)
{
    int e = blockIdx.x * blockDim.x + threadIdx.x;
    if (e >= EE) return;
    atomicMax(&g_last_s[src[e]], e);
    atomicMax(&g_last_g[dst[e]], e);
}

// ----------------- GEMM machinery -----------------
__device__ __forceinline__ void mma_tf32(float* c, const uint32_t* a, const uint32_t* b) {
    asm volatile("mma.sync.aligned.m16n8k8.row.col.f32.tf32.tf32.f32 "
                 "{%0,%1,%2,%3}, {%4,%5,%6,%7}, {%8,%9}, {%0,%1,%2,%3};"
                 : "+f"(c[0]), "+f"(c[1]), "+f"(c[2]), "+f"(c[3])
                 : "r"(a[0]), "r"(a[1]), "r"(a[2]), "r"(a[3]),
                   "r"(b[0]), "r"(b[1]));
}
__device__ __forceinline__ void cp_async16(uint32_t dst, const void* src, int sz) {
    asm volatile("cp.async.cg.shared.global [%0], [%1], 16, %2;"
                 :: "r"(dst), "l"(src), "r"(sz) : "memory");
}
__device__ __forceinline__ void cp_commit() { asm volatile("cp.async.commit_group;" ::: "memory"); }
template<int N> __device__ __forceinline__ void cp_wait() {
    asm volatile("cp.async.wait_group %0;" :: "n"(N) : "memory");
}
__device__ __forceinline__ uint32_t smem_u32(const void* p) {
    uint32_t a;
    asm("{ .reg .u64 t; cvta.to.shared.u64 t, %1; cvt.u32.u64 %0, t; }" : "=r"(a) : "l"(p));
    return a;
}

#define ASTRIDE 40
#define AWORDS (128*ASTRIDE)               // 5120
#define BSTRIDE 72
#define BWORDS (32*BSTRIDE)                // 2304
#define STAGE_WORDS (AWORDS + BWORDS)      // 7424
#define NSTAGE 3
#define SMEM_BYTES (NSTAGE*STAGE_WORDS*4)  // 89088

// MODE 0: A[r][k] = A[r*lda + k]
// MODE 1: A[r][k] = k<200 ? P0[n][k] : P1[n][k-200],  n = r<E?i0[r]:i1[r-E]
// MODE 3: A[r][k] = k<200 ? A[r][k] : k<400 ? A[r_other][k-200] : g_ef[e][k-400]
// MODE 4: A[r][k] = (r<E ? P0[i0[r]] : P1[i1[r-E]])[k]
// B rows K-permuted per 8-slab (k -> (k&1 ? k/2+4 : k/2)) so A frags use LDS.64.
template<int MODE, bool CVTA>
__global__ __launch_bounds__(256) void gemm_tc(
    const float* __restrict__ A, int lda, int Kdim,
    const float* __restrict__ P0, const float* __restrict__ P1,
    const int* __restrict__ i0, const int* __restrict__ i1,
    const float* __restrict__ B0, const float* __restrict__ B1,
    const float* __restrict__ bias0, const float* __restrict__ bias1, int rowSwitch,
    float* __restrict__ C, int Ndim, int act, int roundOut)
{
    extern __shared__ float smf[];
    uint32_t smemBase = smem_u32(smf);

    int blockRow = blockIdx.y * 128;
    int blockCol = blockIdx.x * 64;
    bool firstSide = blockRow < rowSwitch;
    const float* B    = firstSide ? B0 : B1;
    const float* bias = firstSide ? bias0 : bias1;

    int tid = threadIdx.x, lane = tid & 31, warp = tid >> 5;
    int wm = (warp & 3) * 32, wn = (warp >> 2) * 32;
    int g = lane >> 2, tg = lane & 3;

    const float* rp0[4]; const float* rp1[4]; const float* rp2[4];
    #pragma unroll
    for (int i = 0; i < 4; i++) {
        int r = blockRow + ((tid + i*256) >> 3);
        if (MODE == 0) {
            rp0[i] = A + (long)r * lda;
        } else if (MODE == 1) {
            int node = (r < EE) ? i0[r] : i1[r - EE];
            rp0[i] = P0 + (long)node * MM;
            rp1[i] = P1 + (long)node * MM;
        } else if (MODE == 3) {
            int e  = (r < EE) ? r : r - EE;
            int r2 = (r < EE) ? (r + EE) : (r - EE);
            rp0[i] = A + (long)r * MM;
            rp1[i] = A + (long)r2 * MM;
            rp2[i] = g_ef + (long)e * DE;
        } else {
            int node = (r < EE) ? i0[r] : i1[r - EE];
            rp0[i] = ((r < EE) ? P0 : P1) + (long)node * MM;
        }
    }

    auto issue = [&](int t) {
        int s = t % NSTAGE;
        uint32_t aB = smemBase + (uint32_t)(s * STAGE_WORDS) * 4u;
        uint32_t bB = aB + AWORDS * 4u;
        int k0 = t * 32;
        #pragma unroll
        for (int i = 0; i < 4; i++) {
            int idx = tid + i*256;
            int rl = idx >> 3, q = idx & 7;
            int k = k0 + q * 4;
            uint32_t dst = aB + (uint32_t)(rl * ASTRIDE + q * 4) * 4u;
            const float* src; int sz = 16;
            if (MODE == 0) {
                src = rp0[i] + k; if (k >= Kdim) sz = 0;
            } else if (MODE == 1) {
                src = (k < MM) ? rp0[i] + k : rp1[i] + k - MM;
            } else if (MODE == 3) {
                if (k < MM)        src = rp0[i] + k;
                else if (k < 2*MM) src = rp1[i] + k - MM;
                else { src = rp2[i] + k - 2*MM; if (k >= 2*MM + DE) sz = 0; }
            } else {
                src = rp0[i] + k; if (k >= MM) sz = 0;
            }
            cp_async16(dst, src, sz);
        }
        #pragma unroll
        for (int i = 0; i < 2; i++) {
            int idx = tid + i*256;
            int kr = idx >> 4, n4 = (idx & 15) * 4;
            int k = k0 + kr, n = blockCol + n4;
            int l = kr & 7;
            int phys = (kr & ~7) + ((l & 1) ? (l >> 1) + 4 : (l >> 1));
            uint32_t dst = bB + (uint32_t)(phys * BSTRIDE + n4) * 4u;
            const float* src = B + (long)k * Ndim + n;
            int sz = (k < Kdim && n < Ndim) ? 16 : 0;
            cp_async16(dst, src, sz);
        }
    };

    float acc[2][4][4];
    #pragma unroll
    for (int i = 0; i < 2; i++)
        #pragma unroll
        for (int j = 0; j < 4; j++)
            #pragma unroll
            for (int q = 0; q < 4; q++) acc[i][j][q] = 0.0f;

    int nT = (Kdim + 31) / 32;
    issue(0); cp_commit();
    if (nT > 1) issue(1);
    cp_commit();

    uint32_t afr[2][2][4], bfr[2][4][2];
    for (int t = 0; t < nT; t++) {
        cp_wait<1>();
        __syncthreads();
        if (t + 2 < nT) issue(t + 2);
        cp_commit();

        const uint32_t* Asm = (const uint32_t*)smf + (t % NSTAGE) * STAGE_WORDS;
        const uint32_t* Bsm = Asm + AWORDS;

        auto loadFrag = [&](int ks, int bf) {
            #pragma unroll
            for (int mt = 0; mt < 2; mt++) {
                int mr = wm + mt*16 + g;
                uint2 v0 = *(const uint2*)&Asm[(mr    ) * ASTRIDE + ks*8 + 2*tg];
                uint2 v1 = *(const uint2*)&Asm[(mr + 8) * ASTRIDE + ks*8 + 2*tg];
                if (CVTA) {
                    afr[bf][mt][0] = f2tf32(__uint_as_float(v0.x));
                    afr[bf][mt][2] = f2tf32(__uint_as_float(v0.y));
                    afr[bf][mt][1] = f2tf32(__uint_as_float(v1.x));
                    afr[bf][mt][3] = f2tf32(__uint_as_float(v1.y));
                } else {
                    afr[bf][mt][0] = v0.x; afr[bf][mt][2] = v0.y;
                    afr[bf][mt][1] = v1.x; afr[bf][mt][3] = v1.y;
                }
            }
            #pragma unroll
            for (int nt = 0; nt < 4; nt++) {
                int nc = wn + nt*8 + g;
                bfr[bf][nt][0] = Bsm[(ks*8 + tg) * BSTRIDE + nc];
                bfr[bf][nt][1] = Bsm[(ks*8 + tg + 4) * BSTRIDE + nc];
            }
        };

        loadFrag(0, 0);
        #pragma unroll
        for (int ks = 0; ks < 4; ks++) {
            int cur = ks & 1;
            if (ks < 3) loadFrag(ks + 1, cur ^ 1);
            #pragma unroll
            for (int mt = 0; mt < 2; mt++)
                #pragma unroll
                for (int nt = 0; nt < 4; nt++)
                    mma_tf32(acc[mt][nt], afr[cur][mt], bfr[cur][nt]);
        }
    }

    #pragma unroll
    for (int mt = 0; mt < 2; mt++) {
        #pragma unroll
        for (int nt = 0; nt < 4; nt++) {
            int r0 = blockRow + wm + mt*16 + g;
            int c0 = blockCol + wn + nt*8 + tg*2;
            float bv0 = 0.0f, bv1 = 0.0f;
            if (bias) {
                if (c0     < Ndim) bv0 = bias[c0];
                if (c0 + 1 < Ndim) bv1 = bias[c0 + 1];
            }
            #pragma unroll
            for (int q = 0; q < 4; q++) {
                int r = r0 + (q >> 1) * 8;
                int c = c0 + (q & 1);
                if (c >= Ndim) continue;
                float v = acc[mt][nt][q] + ((q & 1) ? bv1 : bv0);
                if (act == 1) v = tanhf(v);
                else if (act == 2) v = fmaxf(v, 0.0f);
                else if (act == 3 && c >= 600) v = tanhf(v);
                if (roundOut) v = roundtf(v);
                C[(long)r * Ndim + c] = v;
            }
        }
    }
}

// ----------------- prep_A3 -----------------
__global__ void prep_A3_kernel(const float* __restrict__ mem_s, const float* __restrict__ mem_g,
                               const int* __restrict__ src, const int* __restrict__ dst,
                               const int* __restrict__ neg)
{
    int r = blockIdx.x * 8 + (threadIdx.x >> 5);
    int lane = threadIdx.x & 31;
    if (r >= E3) return;
    int idx = (r < EE) ? src[r] : ((r < E2) ? dst[r - EE] : neg[r - E2]);
    const float4* ps = (const float4*)(mem_s + (long)idx * MM);
    const float4* pg = (const float4*)(mem_g + (long)idx * MM);
    const float4* ds = (const float4*)(g_delta_s + (long)idx * MM);
    const float4* dg = (const float4*)(g_delta_g + (long)idx * MM);
    float4* o = (float4*)(g_A3 + (long)r * 400);
    #pragma unroll
    for (int c = lane; c < 100; c += 32) {
        float4 a = (c < 50) ? ps[c] : pg[c - 50];
        float4 d = (c < 50) ? ds[c] : dg[c - 50];
        o[c] = make_float4(roundtf(a.x + d.x), roundtf(a.y + d.y),
                           roundtf(a.z + d.z), roundtf(a.w + d.w));
    }
}

// ----------------- GRU + neighbor-propagation scatter -----------------
__device__ __forceinline__ float sigmoidf_(float x) { return 1.0f / (1.0f + expf(-x)); }

__global__ void gru_scatter_kernel(const float* __restrict__ mem_s, const float* __restrict__ mem_g,
                                   const int* __restrict__ src, const int* __restrict__ dst,
                                   const int* __restrict__ neighbors,
                                   const float* __restrict__ times,
                                   const float* __restrict__ lu_s, const float* __restrict__ lu_g)
{
    int row = blockIdx.x;
    bool sideS = (row < EE);
    int e = sideS ? row : (row - EE);
    int node = sideS ? src[e] : dst[e];
    int last = sideS ? g_last_s[node] : g_last_g[node];
    if (last != e) return;
    int m = threadIdx.x;
    if (m >= MM) return;

    float* delta = sideS ? g_delta_s : g_delta_g;
    const float* lu = sideS ? lu_s : lu_g;

    float h = (sideS ? mem_s : mem_g)[(long)node * MM + m];
    long gb = (long)row * 800;
    float rx = g_gxp[gb + m], zx = g_gxp[gb + MM + m], nx = g_gxp[gb + 2*MM + m];
    float p  = g_gxp[gb + 3*MM + m];
    long hb = (long)row * 600;
    float rh = g_gh[hb + m], zh = g_gh[hb + MM + m], nh = g_gh[hb + 2*MM + m];
    float r = sigmoidf_(rx + rh);
    float z = sigmoidf_(zx + zh);
    float n = tanhf(nx + r * nh);
    float new_h = (1.0f - z) * n + z * h;
    atomicAdd(&delta[(long)node * MM + m], new_h - h);

    float t = times[e];
    #pragma unroll
    for (int k = 0; k < KK; k++) {
        int nb = neighbors[(long)node * KK + k];
        float dt = t - lu[nb];
        dt = fminf(fmaxf(dt, 0.0f), 50.0f);
        float decay = expf(-dt * (1.0f / TAU));
        atomicAdd(&delta[(long)nb * MM + m], decay * p);
    }
}

// ----------------- final dot + sigmoid -----------------
__global__ void score_kernel(float* __restrict__ out)
{
    int gw = (blockIdx.x * blockDim.x + threadIdx.x) >> 5;
    int lane = threadIdx.x & 31;
    if (gw >= E2) return;
    int e = (gw < EE) ? gw : (gw - EE);
    const float* u = g_proj + (long)e * DM;
    const float* v = g_proj + (long)((gw < EE) ? (EE + e) : (E2 + e)) * DM;
    float s = 0.0f;
    for (int c = lane; c < DM; c += 32) s += u[c] * v[c];
    #pragma unroll
    for (int off = 16; off > 0; off >>= 1) s += __shfl_down_sync(0xffffffffu, s, off);
    if (lane == 0) out[gw] = 1.0f / (1.0f + expf(-s));
}

// ----------------- launch -----------------
extern "C" void kernel_launch(void* const* d_in, const int* in_sizes, int n_in,
                              void* d_out, int out_size)
{
    const float* mem_s   = (const float*)d_in[0];
    const float* mem_g   = (const float*)d_in[1];
    const float* lu_s    = (const float*)d_in[2];
    const float* lu_g    = (const float*)d_in[3];
    const float* efeats  = (const float*)d_in[4];
    const float* etimes  = (const float*)d_in[5];
    const int*   src     = (const int*)d_in[6];
    const int*   dst     = (const int*)d_in[7];
    const int*   neg     = (const int*)d_in[8];
    const int*   eidx    = (const int*)d_in[9];
    const int*   nbrs    = (const int*)d_in[10];
    const float* W_merge = (const float*)d_in[11];
    const float* b_merge = (const float*)d_in[12];
    const float* W_msg   = (const float*)d_in[13];
    const float* b_msg   = (const float*)d_in[14];
    const float* Wx_s    = (const float*)d_in[15];
    const float* Wh_s    = (const float*)d_in[16];
    const float* bg_s    = (const float*)d_in[17];
    const float* Wx_g    = (const float*)d_in[18];
    const float* Wh_g    = (const float*)d_in[19];
    const float* bg_g    = (const float*)d_in[20];
    const float* Wp_s    = (const float*)d_in[21];
    const float* Wp_g    = (const float*)d_in[22];
    const float* W_s     = (const float*)d_in[23];
    const float* W_g     = (const float*)d_in[24];
    float* out = (float*)d_out;

    float *pMerged12, *pMsgs, *pGh, *pGxp, *pA3, *pMerged3, *pProj, *pW, *pWxp, *pBxp;
    cudaGetSymbolAddress((void**)&pMerged12, g_merged12);
    cudaGetSymbolAddress((void**)&pMsgs,     g_msgs);
    cudaGetSymbolAddress((void**)&pGh,       g_gh);
    cudaGetSymbolAddress((void**)&pGxp,      g_gxp);
    cudaGetSymbolAddress((void**)&pA3,       g_A3);
    cudaGetSymbolAddress((void**)&pMerged3,  g_merged3);
    cudaGetSymbolAddress((void**)&pProj,     g_proj);
    cudaGetSymbolAddress((void**)&pW,        g_wcvt);
    cudaGetSymbolAddress((void**)&pWxp,      g_wxp);
    cudaGetSymbolAddress((void**)&pBxp,      g_bxp);

    cudaFuncSetAttribute(gemm_tc<0,false>, cudaFuncAttributeMaxDynamicSharedMemorySize, SMEM_BYTES);
    cudaFuncSetAttribute(gemm_tc<1,true>,  cudaFuncAttributeMaxDynamicSharedMemorySize, SMEM_BYTES);
    cudaFuncSetAttribute(gemm_tc<3,false>, cudaFuncAttributeMaxDynamicSharedMemorySize, SMEM_BYTES);
    cudaFuncSetAttribute(gemm_tc<4,true>,  cudaFuncAttributeMaxDynamicSharedMemorySize, SMEM_BYTES);

    const int BIG = 1 << 30;
    const float* cWm   = pW + OFF_WMERGE;
    const float* cWmsg = pW + OFF_WMSG;
    const float* cWhs  = pW + OFF_WHS;
    const float* cWhg  = pW + OFF_WHG;
    const float* cWs   = pW + OFF_WS;
    const float* cWg   = pW + OFF_WG;

    // L1: all weight/ef conversions in one launch
    combo1_kernel<<<NB_W + NB_XP + NB_EF, 256>>>(
        W_merge, W_msg, Wh_s, Wh_g, W_s, W_g,
        Wx_s, Wp_s, Wx_g, Wp_g, bg_s, bg_g, efeats, eidx);

    // L2/L3: zero only READ rows + last-occurrence
    zero_init_kernel<<<NZTASKS / 8, 256>>>(src, dst, neg);
    last_occ_kernel<<<(EE + 255) / 256, 256>>>(src, dst);

    // L4: merge12 = round(tanh([ms|mg][src/dst] @ Wm + b))   [E2 x 400]x[400 x 200]
    gemm_tc<1,true><<<dim3(4, E2/128), 256, SMEM_BYTES>>>(
        nullptr, 0, 400, mem_s, mem_g, src, dst,
        cWm, cWm, b_merge, b_merge, BIG, pMerged12, MM, 1, 1);

    // L5: gh = h @ Wh   [E2 x 200]x[200 x 600]
    gemm_tc<4,true><<<dim3(10, E2/128), 256, SMEM_BYTES>>>(
        nullptr, 0, 200, mem_s, mem_g, src, dst,
        cWhs, cWhg, nullptr, nullptr, EE, pGh, 600, 0, 0);

    // L6: msgs = round(relu(concat @ Wmsg + b))   [E2 x 572]x[572 x 100]
    gemm_tc<3,false><<<dim3(2, E2/128), 256, SMEM_BYTES>>>(
        pMerged12, 0, 572, nullptr, nullptr, nullptr, nullptr,
        cWmsg, cWmsg, b_msg, b_msg, BIG, pMsgs, DM, 2, 1);

    // L7: gxp = msgs @ [Wx|Wp] + [bg|0]; tanh cols>=600   [E2 x 100]x[100 x 800]
    gemm_tc<0,false><<<dim3(13, E2/128), 256, SMEM_BYTES>>>(
        pMsgs, DM, DM, nullptr, nullptr, nullptr, nullptr,
        pWxp, pWxp + 80000, pBxp, pBxp + 800, EE, pGxp, 800, 3, 0);

    // L8: GRU elementwise + scatter
    gru_scatter_kernel<<<E2, 256>>>(mem_s, mem_g, src, dst, nbrs, etimes, lu_s, lu_g);

    // L9: A3 = round(mem+delta)
    prep_A3_kernel<<<E3/8, 256>>>(mem_s, mem_g, src, dst, neg);

    // L10: merged3 = round(tanh(A3 @ Wm + b))   [E3 x 400]x[400 x 200]
    gemm_tc<0,false><<<dim3(4, E3/128), 256, SMEM_BYTES>>>(
        pA3, 400, 400, nullptr, nullptr, nullptr, nullptr,
        cWm, cWm, b_merge, b_merge, BIG, pMerged3, MM, 1, 1);

    // L11: proj = merged3 @ (W_s | W_g)   [E3 x 200]x[200 x 100]
    gemm_tc<0,false><<<dim3(2, E3/128), 256, SMEM_BYTES>>>(
        pMerged3, MM, MM, nullptr, nullptr, nullptr, nullptr,
        cWs, cWg, nullptr, nullptr, EE, pProj, DM, 0, 0);

    // L12: score
    score_kernel<<<(E2 * 32 + 255) / 256, 256>>>(out);
}

// round 14
// speedup vs baseline: 1.2464x; 1.0919x over previous
#include <cuda_runtime.h>
#include <cuda_bf16.h>
#include <cstdint>

// Problem constants
#define NN 200000
#define MM 200
#define DM 100
#define DE 172
#define EE 8192
#define KK 10
#define TAU 2.0f

#define E2 (2*EE)     // 16384
#define E3 (3*EE)     // 24576

// ----------------- persistent scratch (zero-initialized at load) -----------------
__device__ float g_merged12[E2 * MM];
__device__ float g_msgs[E2 * DM];
__device__ float g_gh[E2 * 600];
__device__ float g_gxp[E2 * 800];      // [rx zx nx | prop] fused
__device__ float g_delta_s[(long)NN * MM];
__device__ float g_delta_g[(long)NN * MM];
__device__ int   g_last_s[NN];
__device__ int   g_last_g[NN];
__device__ float g_A3[E3 * 400];
__device__ float g_merged3[E3 * MM];
__device__ float g_proj[E3 * DM];
__device__ float g_ef[EE * DE];

// tf32-rounded weight copies (concatenated)
#define OFF_WMERGE 0
#define OFF_WMSG   80000
#define OFF_WHS    137200
#define OFF_WHG    257200
#define OFF_WS     377200
#define OFF_WG     397200
#define WCVT_TOTAL 417200
__device__ float g_wcvt[WCVT_TOTAL];
__device__ float g_wxp[2 * 100 * 800];   // [Wx|Wp] per side, tf32-rounded
__device__ float g_bxp[2 * 800];         // [bg|0] per side

__device__ __forceinline__ uint32_t f2tf32(float f) {
    uint32_t r;
    asm("cvt.rna.tf32.f32 %0, %1;" : "=r"(r) : "f"(f));
    return r;
}
__device__ __forceinline__ float roundtf(float f) { return __uint_as_float(f2tf32(f)); }

// ----------------- combo1: cvt_weights + cvt_xp + prep_ef -----------------
#define NB_W  ((WCVT_TOTAL + 255) / 256)   // 1630
#define NB_XP ((161600 + 255) / 256)       // 632
#define NB_EF (EE / 8)                     // 1024
__global__ void combo1_kernel(const float* __restrict__ wm, const float* __restrict__ wmsg,
                              const float* __restrict__ whs, const float* __restrict__ whg,
                              const float* __restrict__ ws,  const float* __restrict__ wg,
                              const float* __restrict__ wxs, const float* __restrict__ wps,
                              const float* __restrict__ wxg, const float* __restrict__ wpg,
                              const float* __restrict__ bgs, const float* __restrict__ bgg,
                              const float* __restrict__ edge_feats, const int* __restrict__ eidx)
{
    int b = blockIdx.x;
    if (b < NB_W) {
        int i = b * 256 + threadIdx.x;
        if (i >= WCVT_TOTAL) return;
        const float* s; int o;
        if      (i < OFF_WMSG) { s = wm;   o = i - OFF_WMERGE; }
        else if (i < OFF_WHS)  { s = wmsg; o = i - OFF_WMSG; }
        else if (i < OFF_WHG)  { s = whs;  o = i - OFF_WHS; }
        else if (i < OFF_WS)   { s = whg;  o = i - OFF_WHG; }
        else if (i < OFF_WG)   { s = ws;   o = i - OFF_WS; }
        else                   { s = wg;   o = i - OFF_WG; }
        g_wcvt[i] = roundtf(s[o]);
    } else if (b < NB_W + NB_XP) {
        int i = (b - NB_W) * 256 + threadIdx.x;
        if (i < 160000) {
            int side = i / 80000, rem = i % 80000;
            int k = rem / 800, n = rem % 800;
            const float* wx = side ? wxg : wxs;
            const float* wp = side ? wpg : wps;
            float v = (n < 600) ? wx[k * 600 + n] : wp[k * 200 + (n - 600)];
            g_wxp[i] = roundtf(v);
        } else if (i < 161600) {
            int j = i - 160000;
            int side = j / 800, n = j % 800;
            const float* bg = side ? bgg : bgs;
            g_bxp[j] = (n < 600) ? bg[n] : 0.0f;
        }
    } else {
        int e = (b - NB_W - NB_XP) * 8 + (threadIdx.x >> 5);
        int lane = threadIdx.x & 31;
        if (e >= EE) return;
        const float4* s = (const float4*)(edge_feats + (long)eidx[e] * DE);
        float4* o = (float4*)(g_ef + (long)e * DE);
        #pragma unroll
        for (int c = lane; c < DE/4; c += 32) {
            float4 v = s[c];
            o[c] = make_float4(roundtf(v.x), roundtf(v.y), roundtf(v.z), roundtf(v.w));
        }
    }
}

// ----------------- zero only the rows that will be READ ({src,dst,neg} x both sides) --
#define NZTASKS (6*EE)   // 49152
__global__ void zero_init_kernel(const int* __restrict__ src, const int* __restrict__ dst,
                                 const int* __restrict__ neg)
{
    int t = blockIdx.x * 8 + (threadIdx.x >> 5);
    int lane = threadIdx.x & 31;
    if (t >= NZTASKS) return;
    int q = (t < E3) ? t : (t - E3);
    float* delta = (t < E3) ? g_delta_s : g_delta_g;
    int node;
    if (q < EE) {
        node = src[q];
        if (t < E3 && lane == 0) g_last_s[node] = -1;
    } else if (q < E2) {
        node = dst[q - EE];
        if (t < E3 && lane == 0) g_last_g[node] = -1;
    } else {
        node = neg[q - E2];
    }
    float4* p = (float4*)(delta + (long)node * MM);
    float4 z = make_float4(0.f, 0.f, 0.f, 0.f);
    #pragma unroll
    for (int c = lane; c < MM/4; c += 32) p[c] = z;
}

__global__ void last_occ_kernel(const int* __restrict__ src, const int* __restrict__ dst)
{
    int e = blockIdx.x * blockDim.x + threadIdx.x;
    if (e >= EE) return;
    atomicMax(&g_last_s[src[e]], e);
    atomicMax(&g_last_g[dst[e]], e);
}

// ----------------- GEMM machinery -----------------
__device__ __forceinline__ void mma_tf32(float* c, const uint32_t* a, const uint32_t* b) {
    asm volatile("mma.sync.aligned.m16n8k8.row.col.f32.tf32.tf32.f32 "
                 "{%0,%1,%2,%3}, {%4,%5,%6,%7}, {%8,%9}, {%0,%1,%2,%3};"
                 : "+f"(c[0]), "+f"(c[1]), "+f"(c[2]), "+f"(c[3])
                 : "r"(a[0]), "r"(a[1]), "r"(a[2]), "r"(a[3]),
                   "r"(b[0]), "r"(b[1]));
}
__device__ __forceinline__ void cp_async16(uint32_t dst, const void* src, int sz) {
    asm volatile("cp.async.cg.shared.global [%0], [%1], 16, %2;"
                 :: "r"(dst), "l"(src), "r"(sz) : "memory");
}
__device__ __forceinline__ void cp_commit() { asm volatile("cp.async.commit_group;" ::: "memory"); }
template<int N> __device__ __forceinline__ void cp_wait() {
    asm volatile("cp.async.wait_group %0;" :: "n"(N) : "memory");
}
__device__ __forceinline__ uint32_t smem_u32(const void* p) {
    uint32_t a;
    asm("{ .reg .u64 t; cvta.to.shared.u64 t, %1; cvt.u32.u64 %0, t; }" : "=r"(a) : "l"(p));
    return a;
}

#define ASTRIDE 40
#define AWORDS (128*ASTRIDE)               // 5120
#define BSTRIDE 72
#define BWORDS (32*BSTRIDE)                // 2304
#define STAGE_WORDS (AWORDS + BWORDS)      // 7424
#define NSTAGE 2
#define SMEM_BYTES (NSTAGE*STAGE_WORDS*4)  // 59392 -> 3 CTAs/SM

struct GemmP {
    const float* A; int lda, Kdim;
    const float* P0; const float* P1;
    const int* i0; const int* i1;
    const float* B0; const float* B1;
    const float* bias0; const float* bias1; int rowSwitch;
    float* C; int Ndim, act, roundOut;
};

// MODE 0: A[r][k] = A[r*lda + k]
// MODE 1: A[r][k] = k<200 ? P0[n][k] : P1[n][k-200],  n = r<E?i0[r]:i1[r-E]
// MODE 3: A[r][k] = k<200 ? A[r][k] : k<400 ? A[r_other][k-200] : g_ef[e][k-400]
// MODE 4: A[r][k] = (r<E ? P0[i0[r]] : P1[i1[r-E]])[k]
// B rows K-permuted per 8-slab (k -> (k&1 ? k/2+4 : k/2)) so A frags use LDS.64.
// 2-stage pipeline: wait<0> -> barrier -> issue(t+1) -> compute(t) overlaps one tile.
template<int MODE, bool CVTA>
__device__ void gemm_body(const GemmP& P, int bx, int by, float* smf)
{
    uint32_t smemBase = smem_u32(smf);
    int blockRow = by * 128;
    int blockCol = bx * 64;
    bool firstSide = blockRow < P.rowSwitch;
    const float* B    = firstSide ? P.B0 : P.B1;
    const float* bias = firstSide ? P.bias0 : P.bias1;
    int Kdim = P.Kdim, Ndim = P.Ndim;

    int tid = threadIdx.x, lane = tid & 31, warp = tid >> 5;
    int wm = (warp & 3) * 32, wn = (warp >> 2) * 32;
    int g = lane >> 2, tg = lane & 3;

    const float* rp0[4]; const float* rp1[4]; const float* rp2[4];
    #pragma unroll
    for (int i = 0; i < 4; i++) {
        int r = blockRow + ((tid + i*256) >> 3);
        if (MODE == 0) {
            rp0[i] = P.A + (long)r * P.lda;
        } else if (MODE == 1) {
            int node = (r < EE) ? P.i0[r] : P.i1[r - EE];
            rp0[i] = P.P0 + (long)node * MM;
            rp1[i] = P.P1 + (long)node * MM;
        } else if (MODE == 3) {
            int e  = (r < EE) ? r : r - EE;
            int r2 = (r < EE) ? (r + EE) : (r - EE);
            rp0[i] = P.A + (long)r * MM;
            rp1[i] = P.A + (long)r2 * MM;
            rp2[i] = g_ef + (long)e * DE;
        } else {
            int node = (r < EE) ? P.i0[r] : P.i1[r - EE];
            rp0[i] = ((r < EE) ? P.P0 : P.P1) + (long)node * MM;
        }
    }

    auto issue = [&](int t) {
        int s = t & 1;
        uint32_t aB = smemBase + (uint32_t)(s * STAGE_WORDS) * 4u;
        uint32_t bB = aB + AWORDS * 4u;
        int k0 = t * 32;
        #pragma unroll
        for (int i = 0; i < 4; i++) {
            int idx = tid + i*256;
            int rl = idx >> 3, q = idx & 7;
            int k = k0 + q * 4;
            uint32_t dst = aB + (uint32_t)(rl * ASTRIDE + q * 4) * 4u;
            const float* src; int sz = 16;
            if (MODE == 0) {
                src = rp0[i] + k; if (k >= Kdim) sz = 0;
            } else if (MODE == 1) {
                src = (k < MM) ? rp0[i] + k : rp1[i] + k - MM;
            } else if (MODE == 3) {
                if (k < MM)        src = rp0[i] + k;
                else if (k < 2*MM) src = rp1[i] + k - MM;
                else { src = rp2[i] + k - 2*MM; if (k >= 2*MM + DE) sz = 0; }
            } else {
                src = rp0[i] + k; if (k >= MM) sz = 0;
            }
            cp_async16(dst, src, sz);
        }
        #pragma unroll
        for (int i = 0; i < 2; i++) {
            int idx = tid + i*256;
            int kr = idx >> 4, n4 = (idx & 15) * 4;
            int k = k0 + kr, n = blockCol + n4;
            int l = kr & 7;
            int phys = (kr & ~7) + ((l & 1) ? (l >> 1) + 4 : (l >> 1));
            uint32_t dst = bB + (uint32_t)(phys * BSTRIDE + n4) * 4u;
            const float* src = B + (long)k * Ndim + n;
            int sz = (k < Kdim && n < Ndim) ? 16 : 0;
            cp_async16(dst, src, sz);
        }
    };

    float acc[2][4][4];
    #pragma unroll
    for (int i = 0; i < 2; i++)
        #pragma unroll
        for (int j = 0; j < 4; j++)
            #pragma unroll
            for (int q = 0; q < 4; q++) acc[i][j][q] = 0.0f;

    int nT = (Kdim + 31) / 32;
    issue(0); cp_commit();

    uint32_t afr[2][2][4], bfr[2][4][2];
    for (int t = 0; t < nT; t++) {
        cp_wait<0>();          // group t (only in flight) landed
        __syncthreads();       // all warps done reading buffer (t+1)&1 from iter t-1
        if (t + 1 < nT) { issue(t + 1); cp_commit(); }   // overlaps compute below

        const uint32_t* Asm = (const uint32_t*)smf + (t & 1) * STAGE_WORDS;
        const uint32_t* Bsm = Asm + AWORDS;

        auto loadFrag = [&](int ks, int bf) {
            #pragma unroll
            for (int mt = 0; mt < 2; mt++) {
                int mr = wm + mt*16 + g;
                uint2 v0 = *(const uint2*)&Asm[(mr    ) * ASTRIDE + ks*8 + 2*tg];
                uint2 v1 = *(const uint2*)&Asm[(mr + 8) * ASTRIDE + ks*8 + 2*tg];
                if (CVTA) {
                    afr[bf][mt][0] = f2tf32(__uint_as_float(v0.x));
                    afr[bf][mt][2] = f2tf32(__uint_as_float(v0.y));
                    afr[bf][mt][1] = f2tf32(__uint_as_float(v1.x));
                    afr[bf][mt][3] = f2tf32(__uint_as_float(v1.y));
                } else {
                    afr[bf][mt][0] = v0.x; afr[bf][mt][2] = v0.y;
                    afr[bf][mt][1] = v1.x; afr[bf][mt][3] = v1.y;
                }
            }
            #pragma unroll
            for (int nt = 0; nt < 4; nt++) {
                int nc = wn + nt*8 + g;
                bfr[bf][nt][0] = Bsm[(ks*8 + tg) * BSTRIDE + nc];
                bfr[bf][nt][1] = Bsm[(ks*8 + tg + 4) * BSTRIDE + nc];
            }
        };

        loadFrag(0, 0);
        #pragma unroll
        for (int ks = 0; ks < 4; ks++) {
            int cur = ks & 1;
            if (ks < 3) loadFrag(ks + 1, cur ^ 1);
            #pragma unroll
            for (int mt = 0; mt < 2; mt++)
                #pragma unroll
                for (int nt = 0; nt < 4; nt++)
                    mma_tf32(acc[mt][nt], afr[cur][mt], bfr[cur][nt]);
        }
    }

    #pragma unroll
    for (int mt = 0; mt < 2; mt++) {
        #pragma unroll
        for (int nt = 0; nt < 4; nt++) {
            int r0 = blockRow + wm + mt*16 + g;
            int c0 = blockCol + wn + nt*8 + tg*2;
            float bv0 = 0.0f, bv1 = 0.0f;
            if (bias) {
                if (c0     < Ndim) bv0 = bias[c0];
                if (c0 + 1 < Ndim) bv1 = bias[c0 + 1];
            }
            #pragma unroll
            for (int q = 0; q < 4; q++) {
                int r = r0 + (q >> 1) * 8;
                int c = c0 + (q & 1);
                if (c >= Ndim) continue;
                float v = acc[mt][nt][q] + ((q & 1) ? bv1 : bv0);
                if (P.act == 1) v = tanhf(v);
                else if (P.act == 2) v = fmaxf(v, 0.0f);
                else if (P.act == 3 && c >= 600) v = tanhf(v);
                if (P.roundOut) v = roundtf(v);
                P.C[(long)r * Ndim + c] = v;
            }
        }
    }
}

template<int MODE, bool CVTA>
__global__ __launch_bounds__(256) void gemm_tc(GemmP P)
{
    extern __shared__ float smf[];
    gemm_body<MODE, CVTA>(P, blockIdx.x, blockIdx.y, smf);
}

// Fused merge12 + gh (both GEMMs, identical resource footprint)
#define G1 (4 * (E2/128))      // 512   merge12
#define G2 (10 * (E2/128))     // 1280  gh
__global__ __launch_bounds__(256) void gemm_pair_kernel(GemmP P1, GemmP P2)
{
    extern __shared__ float smf[];
    int b = blockIdx.x;
    if (b < G1) gemm_body<1, true>(P1, b % 4, b / 4, smf);
    else        { int vb = b - G1; gemm_body<4, true>(P2, vb % 10, vb / 10, smf); }
}

// ----------------- prep_A3 -----------------
__global__ void prep_A3_kernel(const float* __restrict__ mem_s, const float* __restrict__ mem_g,
                               const int* __restrict__ src, const int* __restrict__ dst,
                               const int* __restrict__ neg)
{
    int r = blockIdx.x * 8 + (threadIdx.x >> 5);
    int lane = threadIdx.x & 31;
    if (r >= E3) return;
    int idx = (r < EE) ? src[r] : ((r < E2) ? dst[r - EE] : neg[r - E2]);
    const float4* ps = (const float4*)(mem_s + (long)idx * MM);
    const float4* pg = (const float4*)(mem_g + (long)idx * MM);
    const float4* ds = (const float4*)(g_delta_s + (long)idx * MM);
    const float4* dg = (const float4*)(g_delta_g + (long)idx * MM);
    float4* o = (float4*)(g_A3 + (long)r * 400);
    #pragma unroll
    for (int c = lane; c < 100; c += 32) {
        float4 a = (c < 50) ? ps[c] : pg[c - 50];
        float4 d = (c < 50) ? ds[c] : dg[c - 50];
        o[c] = make_float4(roundtf(a.x + d.x), roundtf(a.y + d.y),
                           roundtf(a.z + d.z), roundtf(a.w + d.w));
    }
}

// ----------------- GRU + neighbor-propagation scatter -----------------
__device__ __forceinline__ float sigmoidf_(float x) { return 1.0f / (1.0f + expf(-x)); }

__global__ void gru_scatter_kernel(const float* __restrict__ mem_s, const float* __restrict__ mem_g,
                                   const int* __restrict__ src, const int* __restrict__ dst,
                                   const int* __restrict__ neighbors,
                                   const float* __restrict__ times,
                                   const float* __restrict__ lu_s, const float* __restrict__ lu_g)
{
    int row = blockIdx.x;
    bool sideS = (row < EE);
    int e = sideS ? row : (row - EE);
    int node = sideS ? src[e] : dst[e];
    int last = sideS ? g_last_s[node] : g_last_g[node];
    if (last != e) return;
    int m = threadIdx.x;
    if (m >= MM) return;

    float* delta = sideS ? g_delta_s : g_delta_g;
    const float* lu = sideS ? lu_s : lu_g;

    float h = (sideS ? mem_s : mem_g)[(long)node * MM + m];
    long gb = (long)row * 800;
    float rx = g_gxp[gb + m], zx = g_gxp[gb + MM + m], nx = g_gxp[gb + 2*MM + m];
    float p  = g_gxp[gb + 3*MM + m];
    long hb = (long)row * 600;
    float rh = g_gh[hb + m], zh = g_gh[hb + MM + m], nh = g_gh[hb + 2*MM + m];
    float r = sigmoidf_(rx + rh);
    float z = sigmoidf_(zx + zh);
    float n = tanhf(nx + r * nh);
    float new_h = (1.0f - z) * n + z * h;
    atomicAdd(&delta[(long)node * MM + m], new_h - h);

    float t = times[e];
    #pragma unroll
    for (int k = 0; k < KK; k++) {
        int nb = neighbors[(long)node * KK + k];
        float dt = t - lu[nb];
        dt = fminf(fmaxf(dt, 0.0f), 50.0f);
        float decay = expf(-dt * (1.0f / TAU));
        atomicAdd(&delta[(long)nb * MM + m], decay * p);
    }
}

// ----------------- final dot + sigmoid -----------------
__global__ void score_kernel(float* __restrict__ out)
{
    int gw = (blockIdx.x * blockDim.x + threadIdx.x) >> 5;
    int lane = threadIdx.x & 31;
    if (gw >= E2) return;
    int e = (gw < EE) ? gw : (gw - EE);
    const float* u = g_proj + (long)e * DM;
    const float* v = g_proj + (long)((gw < EE) ? (EE + e) : (E2 + e)) * DM;
    float s = 0.0f;
    for (int c = lane; c < DM; c += 32) s += u[c] * v[c];
    #pragma unroll
    for (int off = 16; off > 0; off >>= 1) s += __shfl_down_sync(0xffffffffu, s, off);
    if (lane == 0) out[gw] = 1.0f / (1.0f + expf(-s));
}

// ----------------- launch -----------------
extern "C" void kernel_launch(void* const* d_in, const int* in_sizes, int n_in,
                              void* d_out, int out_size)
{
    const float* mem_s   = (const float*)d_in[0];
    const float* mem_g   = (const float*)d_in[1];
    const float* lu_s    = (const float*)d_in[2];
    const float* lu_g    = (const float*)d_in[3];
    const float* efeats  = (const float*)d_in[4];
    const float* etimes  = (const float*)d_in[5];
    const int*   src     = (const int*)d_in[6];
    const int*   dst     = (const int*)d_in[7];
    const int*   neg     = (const int*)d_in[8];
    const int*   eidx    = (const int*)d_in[9];
    const int*   nbrs    = (const int*)d_in[10];
    const float* W_merge = (const float*)d_in[11];
    const float* b_merge = (const float*)d_in[12];
    const float* W_msg   = (const float*)d_in[13];
    const float* b_msg   = (const float*)d_in[14];
    const float* Wx_s    = (const float*)d_in[15];
    const float* Wh_s    = (const float*)d_in[16];
    const float* bg_s    = (const float*)d_in[17];
    const float* Wx_g    = (const float*)d_in[18];
    const float* Wh_g    = (const float*)d_in[19];
    const float* bg_g    = (const float*)d_in[20];
    const float* Wp_s    = (const float*)d_in[21];
    const float* Wp_g    = (const float*)d_in[22];
    const float* W_s     = (const float*)d_in[23];
    const float* W_g     = (const float*)d_in[24];
    float* out = (float*)d_out;

    float *pMerged12, *pMsgs, *pGh, *pGxp, *pA3, *pMerged3, *pProj, *pW, *pWxp, *pBxp;
    cudaGetSymbolAddress((void**)&pMerged12, g_merged12);
    cudaGetSymbolAddress((void**)&pMsgs,     g_msgs);
    cudaGetSymbolAddress((void**)&pGh,       g_gh);
    cudaGetSymbolAddress((void**)&pGxp,      g_gxp);
    cudaGetSymbolAddress((void**)&pA3,       g_A3);
    cudaGetSymbolAddress((void**)&pMerged3,  g_merged3);
    cudaGetSymbolAddress((void**)&pProj,     g_proj);
    cudaGetSymbolAddress((void**)&pW,        g_wcvt);
    cudaGetSymbolAddress((void**)&pWxp,      g_wxp);
    cudaGetSymbolAddress((void**)&pBxp,      g_bxp);

    cudaFuncSetAttribute(gemm_tc<0,false>,  cudaFuncAttributeMaxDynamicSharedMemorySize, SMEM_BYTES);
    cudaFuncSetAttribute(gemm_tc<3,false>,  cudaFuncAttributeMaxDynamicSharedMemorySize, SMEM_BYTES);
    cudaFuncSetAttribute(gemm_pair_kernel,  cudaFuncAttributeMaxDynamicSharedMemorySize, SMEM_BYTES);

    const int BIG = 1 << 30;
    const float* cWm   = pW + OFF_WMERGE;
    const float* cWmsg = pW + OFF_WMSG;
    const float* cWhs  = pW + OFF_WHS;
    const float* cWhg  = pW + OFF_WHG;
    const float* cWs   = pW + OFF_WS;
    const float* cWg   = pW + OFF_WG;

    // L1: all weight/ef conversions in one launch
    combo1_kernel<<<NB_W + NB_XP + NB_EF, 256>>>(
        W_merge, W_msg, Wh_s, Wh_g, W_s, W_g,
        Wx_s, Wp_s, Wx_g, Wp_g, bg_s, bg_g, efeats, eidx);

    // L2/L3: zero only READ rows + last-occurrence
    zero_init_kernel<<<NZTASKS / 8, 256>>>(src, dst, neg);
    last_occ_kernel<<<(EE + 255) / 256, 256>>>(src, dst);

    // L4: merge12 + gh fused (both independent GEMMs, same footprint)
    GemmP Pm12 = { nullptr, 0, 400, mem_s, mem_g, src, dst,
                   cWm, cWm, b_merge, b_merge, BIG, pMerged12, MM, 1, 1 };
    GemmP Pgh  = { nullptr, 0, 200, mem_s, mem_g, src, dst,
                   cWhs, cWhg, nullptr, nullptr, EE, pGh, 600, 0, 0 };
    gemm_pair_kernel<<<G1 + G2, 256, SMEM_BYTES>>>(Pm12, Pgh);

    // L5: msgs = round(relu(concat @ Wmsg + b))   [E2 x 572]x[572 x 100]
    GemmP Pmsg = { pMerged12, 0, 572, nullptr, nullptr, nullptr, nullptr,
                   cWmsg, cWmsg, b_msg, b_msg, BIG, pMsgs, DM, 2, 1 };
    gemm_tc<3,false><<<dim3(2, E2/128), 256, SMEM_BYTES>>>(Pmsg);

    // L6: gxp = msgs @ [Wx|Wp] + [bg|0]; tanh cols>=600   [E2 x 100]x[100 x 800]
    GemmP Pgxp = { pMsgs, DM, DM, nullptr, nullptr, nullptr, nullptr,
                   pWxp, pWxp + 80000, pBxp, pBxp + 800, EE, pGxp, 800, 3, 0 };
    gemm_tc<0,false><<<dim3(13, E2/128), 256, SMEM_BYTES>>>(Pgxp);

    // L7: GRU elementwise + scatter
    gru_scatter_kernel<<<E2, 256>>>(mem_s, mem_g, src, dst, nbrs, etimes, lu_s, lu_g);

    // L8: A3 = round(mem+delta)
    prep_A3_kernel<<<E3/8, 256>>>(mem_s, mem_g, src, dst, neg);

    // L9: merged3 = round(tanh(A3 @ Wm + b))   [E3 x 400]x[400 x 200]
    GemmP Pm3 = { pA3, 400, 400, nullptr, nullptr, nullptr, nullptr,
                  cWm, cWm, b_merge, b_merge, BIG, pMerged3, MM, 1, 1 };
    gemm_tc<0,false><<<dim3(4, E3/128), 256, SMEM_BYTES>>>(Pm3);

    // L10: proj = merged3 @ (W_s | W_g)   [E3 x 200]x[200 x 100]
    GemmP Ppr = { pMerged3, MM, MM, nullptr, nullptr, nullptr, nullptr,
                  cWs, cWg, nullptr, nullptr, EE, pProj, DM, 0, 0 };
    gemm_tc<0,false><<<dim3(2, E3/128), 256, SMEM_BYTES>>>(Ppr);

    // L11: score
    score_kernel<<<(E2 * 32 + 255) / 256, 256>>>(out);
}

// round 15
// speedup vs baseline: 1.2760x; 1.0237x over previous
#include <cuda_runtime.h>
#include <cuda_bf16.h>
#include <cstdint>

// Problem constants
#define NN 200000
#define MM 200
#define DM 100
#define DE 172
#define EE 8192
#define KK 10
#define TAU 2.0f

#define E2 (2*EE)     // 16384
#define E3 (3*EE)     // 24576

// ----------------- persistent scratch (zero-initialized at load) -----------------
__device__ float g_merged12[E2 * MM];
__device__ float g_msgs[E2 * DM];
__device__ float g_gh[E2 * 600];
__device__ float g_gxp[E2 * 800];      // [rx zx nx | prop] fused
__device__ float g_delta_s[(long)NN * MM];
__device__ float g_delta_g[(long)NN * MM];
__device__ int   g_last_s[NN];
__device__ int   g_last_g[NN];
__device__ unsigned char g_flag[NN];   // 1 iff node in {src,dst,neg} read-set (idempotent across replays)
__device__ float g_A3[E3 * 400];
__device__ float g_merged3[E3 * MM];
__device__ float g_proj[E3 * DM];
__device__ float g_ef[EE * DE];

// tf32-rounded weight copies (concatenated)
#define OFF_WMERGE 0
#define OFF_WMSG   80000
#define OFF_WHS    137200
#define OFF_WHG    257200
#define OFF_WS     377200
#define OFF_WG     397200
#define WCVT_TOTAL 417200
__device__ float g_wcvt[WCVT_TOTAL];
__device__ float g_wxp[2 * 100 * 800];   // [Wx|Wp] per side, tf32-rounded
__device__ float g_bxp[2 * 800];         // [bg|0] per side

__device__ __forceinline__ uint32_t f2tf32(float f) {
    uint32_t r;
    asm("cvt.rna.tf32.f32 %0, %1;" : "=r"(r) : "f"(f));
    return r;
}
__device__ __forceinline__ float roundtf(float f) { return __uint_as_float(f2tf32(f)); }

// ----------------- combo0: zero_init(+flags) + cvt_weights + cvt_xp + prep_ef --------
// zero blocks FIRST (on the gru critical path). last_occ stays a separate launch:
// its atomicMax races with the -1 init if fused.
#define NZTASKS (6*EE)                     // 49152
#define NB_Z  (NZTASKS / 8)                // 6144
#define NB_W  ((WCVT_TOTAL + 255) / 256)   // 1630
#define NB_XP ((161600 + 255) / 256)       // 632
#define NB_EF (EE / 8)                     // 1024
__global__ void combo0_kernel(const float* __restrict__ wm, const float* __restrict__ wmsg,
                              const float* __restrict__ whs, const float* __restrict__ whg,
                              const float* __restrict__ ws,  const float* __restrict__ wg,
                              const float* __restrict__ wxs, const float* __restrict__ wps,
                              const float* __restrict__ wxg, const float* __restrict__ wpg,
                              const float* __restrict__ bgs, const float* __restrict__ bgg,
                              const float* __restrict__ edge_feats, const int* __restrict__ eidx,
                              const int* __restrict__ src, const int* __restrict__ dst,
                              const int* __restrict__ neg)
{
    int b = blockIdx.x;
    if (b < NB_Z) {
        int t = b * 8 + (threadIdx.x >> 5);
        int lane = threadIdx.x & 31;
        if (t >= NZTASKS) return;
        int q = (t < E3) ? t : (t - E3);
        float* delta = (t < E3) ? g_delta_s : g_delta_g;
        int node;
        if (q < EE) {
            node = src[q];
            if (t < E3 && lane == 0) g_last_s[node] = -1;
        } else if (q < E2) {
            node = dst[q - EE];
            if (t < E3 && lane == 0) g_last_g[node] = -1;
        } else {
            node = neg[q - E2];
        }
        if (t < E3 && lane == 1) g_flag[node] = 1;   // read-set marker (same set every replay)
        float4* p = (float4*)(delta + (long)node * MM);
        float4 z = make_float4(0.f, 0.f, 0.f, 0.f);
        #pragma unroll
        for (int c = lane; c < MM/4; c += 32) p[c] = z;
    } else if (b < NB_Z + NB_W) {
        int i = (b - NB_Z) * 256 + threadIdx.x;
        if (i >= WCVT_TOTAL) return;
        const float* s; int o;
        if      (i < OFF_WMSG) { s = wm;   o = i - OFF_WMERGE; }
        else if (i < OFF_WHS)  { s = wmsg; o = i - OFF_WMSG; }
        else if (i < OFF_WHG)  { s = whs;  o = i - OFF_WHS; }
        else if (i < OFF_WS)   { s = whg;  o = i - OFF_WHG; }
        else if (i < OFF_WG)   { s = ws;   o = i - OFF_WS; }
        else                   { s = wg;   o = i - OFF_WG; }
        g_wcvt[i] = roundtf(s[o]);
    } else if (b < NB_Z + NB_W + NB_XP) {
        int i = (b - NB_Z - NB_W) * 256 + threadIdx.x;
        if (i < 160000) {
            int side = i / 80000, rem = i % 80000;
            int k = rem / 800, n = rem % 800;
            const float* wx = side ? wxg : wxs;
            const float* wp = side ? wpg : wps;
            float v = (n < 600) ? wx[k * 600 + n] : wp[k * 200 + (n - 600)];
            g_wxp[i] = roundtf(v);
        } else if (i < 161600) {
            int j = i - 160000;
            int side = j / 800, n = j % 800;
            const float* bg = side ? bgg : bgs;
            g_bxp[j] = (n < 600) ? bg[n] : 0.0f;
        }
    } else {
        int e = (b - NB_Z - NB_W - NB_XP) * 8 + (threadIdx.x >> 5);
        int lane = threadIdx.x & 31;
        if (e >= EE) return;
        const float4* s = (const float4*)(edge_feats + (long)eidx[e] * DE);
        float4* o = (float4*)(g_ef + (long)e * DE);
        #pragma unroll
        for (int c = lane; c < DE/4; c += 32) {
            float4 v = s[c];
            o[c] = make_float4(roundtf(v.x), roundtf(v.y), roundtf(v.z), roundtf(v.w));
        }
    }
}

__global__ void last_occ_kernel(const int* __restrict__ src, const int* __restrict__ dst)
{
    int e = blockIdx.x * blockDim.x + threadIdx.x;
    if (e >= EE) return;
    atomicMax(&g_last_s[src[e]], e);
    atomicMax(&g_last_g[dst[e]], e);
}

// ----------------- GEMM machinery -----------------
__device__ __forceinline__ void mma_tf32(float* c, const uint32_t* a, const uint32_t* b) {
    asm volatile("mma.sync.aligned.m16n8k8.row.col.f32.tf32.tf32.f32 "
                 "{%0,%1,%2,%3}, {%4,%5,%6,%7}, {%8,%9}, {%0,%1,%2,%3};"
                 : "+f"(c[0]), "+f"(c[1]), "+f"(c[2]), "+f"(c[3])
                 : "r"(a[0]), "r"(a[1]), "r"(a[2]), "r"(a[3]),
                   "r"(b[0]), "r"(b[1]));
}
__device__ __forceinline__ void cp_async16(uint32_t dst, const void* src, int sz) {
    asm volatile("cp.async.cg.shared.global [%0], [%1], 16, %2;"
                 :: "r"(dst), "l"(src), "r"(sz) : "memory");
}
__device__ __forceinline__ void cp_commit() { asm volatile("cp.async.commit_group;" ::: "memory"); }
template<int N> __device__ __forceinline__ void cp_wait() {
    asm volatile("cp.async.wait_group %0;" :: "n"(N) : "memory");
}
__device__ __forceinline__ uint32_t smem_u32(const void* p) {
    uint32_t a;
    asm("{ .reg .u64 t; cvta.to.shared.u64 t, %1; cvt.u32.u64 %0, t; }" : "=r"(a) : "l"(p));
    return a;
}

#define ASTRIDE 40
#define AWORDS (128*ASTRIDE)               // 5120
#define BSTRIDE 72
#define BWORDS (32*BSTRIDE)                // 2304
#define STAGE_WORDS (AWORDS + BWORDS)      // 7424
#define NSTAGE 2
#define SMEM_BYTES (NSTAGE*STAGE_WORDS*4)  // 59392 -> 3 CTAs/SM

struct GemmP {
    const float* A; int lda, Kdim;
    const float* P0; const float* P1;
    const int* i0; const int* i1;
    const float* B0; const float* B1;
    const float* bias0; const float* bias1; int rowSwitch;
    float* C; int Ndim, act, roundOut;
};

// MODE 0: A[r][k] = A[r*lda + k]
// MODE 1: A[r][k] = k<200 ? P0[n][k] : P1[n][k-200],  n = r<E?i0[r]:i1[r-E]
// MODE 3: A[r][k] = k<200 ? A[r][k] : k<400 ? A[r_other][k-200] : g_ef[e][k-400]
// MODE 4: A[r][k] = (r<E ? P0[i0[r]] : P1[i1[r-E]])[k]
// B rows K-permuted per 8-slab (k -> (k&1 ? k/2+4 : k/2)) so A frags use LDS.64.
template<int MODE, bool CVTA>
__device__ void gemm_body(const GemmP& P, int bx, int by, float* smf)
{
    uint32_t smemBase = smem_u32(smf);
    int blockRow = by * 128;
    int blockCol = bx * 64;
    bool firstSide = blockRow < P.rowSwitch;
    const float* B    = firstSide ? P.B0 : P.B1;
    const float* bias = firstSide ? P.bias0 : P.bias1;
    int Kdim = P.Kdim, Ndim = P.Ndim;

    int tid = threadIdx.x, lane = tid & 31, warp = tid >> 5;
    int wm = (warp & 3) * 32, wn = (warp >> 2) * 32;
    int g = lane >> 2, tg = lane & 3;

    const float* rp0[4]; const float* rp1[4]; const float* rp2[4];
    #pragma unroll
    for (int i = 0; i < 4; i++) {
        int r = blockRow + ((tid + i*256) >> 3);
        if (MODE == 0) {
            rp0[i] = P.A + (long)r * P.lda;
        } else if (MODE == 1) {
            int node = (r < EE) ? P.i0[r] : P.i1[r - EE];
            rp0[i] = P.P0 + (long)node * MM;
            rp1[i] = P.P1 + (long)node * MM;
        } else if (MODE == 3) {
            int e  = (r < EE) ? r : r - EE;
            int r2 = (r < EE) ? (r + EE) : (r - EE);
            rp0[i] = P.A + (long)r * MM;
            rp1[i] = P.A + (long)r2 * MM;
            rp2[i] = g_ef + (long)e * DE;
        } else {
            int node = (r < EE) ? P.i0[r] : P.i1[r - EE];
            rp0[i] = ((r < EE) ? P.P0 : P.P1) + (long)node * MM;
        }
    }

    auto issue = [&](int t) {
        int s = t & 1;
        uint32_t aB = smemBase + (uint32_t)(s * STAGE_WORDS) * 4u;
        uint32_t bB = aB + AWORDS * 4u;
        int k0 = t * 32;
        #pragma unroll
        for (int i = 0; i < 4; i++) {
            int idx = tid + i*256;
            int rl = idx >> 3, q = idx & 7;
            int k = k0 + q * 4;
            uint32_t dst = aB + (uint32_t)(rl * ASTRIDE + q * 4) * 4u;
            const float* src; int sz = 16;
            if (MODE == 0) {
                src = rp0[i] + k; if (k >= Kdim) sz = 0;
            } else if (MODE == 1) {
                src = (k < MM) ? rp0[i] + k : rp1[i] + k - MM;
            } else if (MODE == 3) {
                if (k < MM)        src = rp0[i] + k;
                else if (k < 2*MM) src = rp1[i] + k - MM;
                else { src = rp2[i] + k - 2*MM; if (k >= 2*MM + DE) sz = 0; }
            } else {
                src = rp0[i] + k; if (k >= MM) sz = 0;
            }
            cp_async16(dst, src, sz);
        }
        #pragma unroll
        for (int i = 0; i < 2; i++) {
            int idx = tid + i*256;
            int kr = idx >> 4, n4 = (idx & 15) * 4;
            int k = k0 + kr, n = blockCol + n4;
            int l = kr & 7;
            int phys = (kr & ~7) + ((l & 1) ? (l >> 1) + 4 : (l >> 1));
            uint32_t dst = bB + (uint32_t)(phys * BSTRIDE + n4) * 4u;
            const float* src = B + (long)k * Ndim + n;
            int sz = (k < Kdim && n < Ndim) ? 16 : 0;
            cp_async16(dst, src, sz);
        }
    };

    float acc[2][4][4];
    #pragma unroll
    for (int i = 0; i < 2; i++)
        #pragma unroll
        for (int j = 0; j < 4; j++)
            #pragma unroll
            for (int q = 0; q < 4; q++) acc[i][j][q] = 0.0f;

    int nT = (Kdim + 31) / 32;
    issue(0); cp_commit();

    uint32_t afr[2][2][4], bfr[2][4][2];
    for (int t = 0; t < nT; t++) {
        cp_wait<0>();
        __syncthreads();
        if (t + 1 < nT) { issue(t + 1); cp_commit(); }

        const uint32_t* Asm = (const uint32_t*)smf + (t & 1) * STAGE_WORDS;
        const uint32_t* Bsm = Asm + AWORDS;

        auto loadFrag = [&](int ks, int bf) {
            #pragma unroll
            for (int mt = 0; mt < 2; mt++) {
                int mr = wm + mt*16 + g;
                uint2 v0 = *(const uint2*)&Asm[(mr    ) * ASTRIDE + ks*8 + 2*tg];
                uint2 v1 = *(const uint2*)&Asm[(mr + 8) * ASTRIDE + ks*8 + 2*tg];
                if (CVTA) {
                    afr[bf][mt][0] = f2tf32(__uint_as_float(v0.x));
                    afr[bf][mt][2] = f2tf32(__uint_as_float(v0.y));
                    afr[bf][mt][1] = f2tf32(__uint_as_float(v1.x));
                    afr[bf][mt][3] = f2tf32(__uint_as_float(v1.y));
                } else {
                    afr[bf][mt][0] = v0.x; afr[bf][mt][2] = v0.y;
                    afr[bf][mt][1] = v1.x; afr[bf][mt][3] = v1.y;
                }
            }
            #pragma unroll
            for (int nt = 0; nt < 4; nt++) {
                int nc = wn + nt*8 + g;
                bfr[bf][nt][0] = Bsm[(ks*8 + tg) * BSTRIDE + nc];
                bfr[bf][nt][1] = Bsm[(ks*8 + tg + 4) * BSTRIDE + nc];
            }
        };

        loadFrag(0, 0);
        #pragma unroll
        for (int ks = 0; ks < 4; ks++) {
            int cur = ks & 1;
            if (ks < 3) loadFrag(ks + 1, cur ^ 1);
            #pragma unroll
            for (int mt = 0; mt < 2; mt++)
                #pragma unroll
                for (int nt = 0; nt < 4; nt++)
                    mma_tf32(acc[mt][nt], afr[cur][mt], bfr[cur][nt]);
        }
    }

    #pragma unroll
    for (int mt = 0; mt < 2; mt++) {
        #pragma unroll
        for (int nt = 0; nt < 4; nt++) {
            int r0 = blockRow + wm + mt*16 + g;
            int c0 = blockCol + wn + nt*8 + tg*2;
            float bv0 = 0.0f, bv1 = 0.0f;
            if (bias) {
                if (c0     < Ndim) bv0 = bias[c0];
                if (c0 + 1 < Ndim) bv1 = bias[c0 + 1];
            }
            #pragma unroll
            for (int q = 0; q < 4; q++) {
                int r = r0 + (q >> 1) * 8;
                int c = c0 + (q & 1);
                if (c >= Ndim) continue;
                float v = acc[mt][nt][q] + ((q & 1) ? bv1 : bv0);
                if (P.act == 1) v = tanhf(v);
                else if (P.act == 2) v = fmaxf(v, 0.0f);
                else if (P.act == 3 && c >= 600) v = tanhf(v);
                if (P.roundOut) v = roundtf(v);
                P.C[(long)r * Ndim + c] = v;
            }
        }
    }
}

template<int MODE, bool CVTA>
__global__ __launch_bounds__(256) void gemm_tc(GemmP P)
{
    extern __shared__ float smf[];
    gemm_body<MODE, CVTA>(P, blockIdx.x, blockIdx.y, smf);
}

// Fused merge12 + gh (both GEMMs, identical resource footprint)
#define G1 (4 * (E2/128))      // 512   merge12
#define G2 (10 * (E2/128))     // 1280  gh
__global__ __launch_bounds__(256) void gemm_pair_kernel(GemmP P1, GemmP P2)
{
    extern __shared__ float smf[];
    int b = blockIdx.x;
    if (b < G1) gemm_body<1, true>(P1, b % 4, b / 4, smf);
    else        { int vb = b - G1; gemm_body<4, true>(P2, vb % 10, vb / 10, smf); }
}

// ----------------- prep_A3 -----------------
__global__ void prep_A3_kernel(const float* __restrict__ mem_s, const float* __restrict__ mem_g,
                               const int* __restrict__ src, const int* __restrict__ dst,
                               const int* __restrict__ neg)
{
    int r = blockIdx.x * 8 + (threadIdx.x >> 5);
    int lane = threadIdx.x & 31;
    if (r >= E3) return;
    int idx = (r < EE) ? src[r] : ((r < E2) ? dst[r - EE] : neg[r - E2]);
    const float4* ps = (const float4*)(mem_s + (long)idx * MM);
    const float4* pg = (const float4*)(mem_g + (long)idx * MM);
    const float4* ds = (const float4*)(g_delta_s + (long)idx * MM);
    const float4* dg = (const float4*)(g_delta_g + (long)idx * MM);
    float4* o = (float4*)(g_A3 + (long)r * 400);
    #pragma unroll
    for (int c = lane; c < 100; c += 32) {
        float4 a = (c < 50) ? ps[c] : pg[c - 50];
        float4 d = (c < 50) ? ds[c] : dg[c - 50];
        o[c] = make_float4(roundtf(a.x + d.x), roundtf(a.y + d.y),
                           roundtf(a.z + d.z), roundtf(a.w + d.w));
    }
}

// ----------------- GRU + neighbor-propagation scatter (dead-scatter skip) -----------
__device__ __forceinline__ float sigmoidf_(float x) { return 1.0f / (1.0f + expf(-x)); }

__global__ void gru_scatter_kernel(const float* __restrict__ mem_s, const float* __restrict__ mem_g,
                                   const int* __restrict__ src, const int* __restrict__ dst,
                                   const int* __restrict__ neighbors,
                                   const float* __restrict__ times,
                                   const float* __restrict__ lu_s, const float* __restrict__ lu_g)
{
    int row = blockIdx.x;
    bool sideS = (row < EE);
    int e = sideS ? row : (row - EE);
    int node = sideS ? src[e] : dst[e];
    int last = sideS ? g_last_s[node] : g_last_g[node];
    if (last != e) return;
    int m = threadIdx.x;
    if (m >= MM) return;

    float* delta = sideS ? g_delta_s : g_delta_g;
    const float* lu = sideS ? lu_s : lu_g;

    float h = (sideS ? mem_s : mem_g)[(long)node * MM + m];
    long gb = (long)row * 800;
    float rx = g_gxp[gb + m], zx = g_gxp[gb + MM + m], nx = g_gxp[gb + 2*MM + m];
    float p  = g_gxp[gb + 3*MM + m];
    long hb = (long)row * 600;
    float rh = g_gh[hb + m], zh = g_gh[hb + MM + m], nh = g_gh[hb + 2*MM + m];
    float r = sigmoidf_(rx + rh);
    float z = sigmoidf_(zx + zh);
    float n = tanhf(nx + r * nh);
    float new_h = (1.0f - z) * n + z * h;
    atomicAdd(&delta[(long)node * MM + m], new_h - h);   // node is in the read-set by construction

    float t = times[e];
    #pragma unroll
    for (int k = 0; k < KK; k++) {
        int nb = neighbors[(long)node * KK + k];
        if (!g_flag[nb]) continue;   // delta row never read -> dead write, skip (warp-uniform)
        float dt = t - lu[nb];
        dt = fminf(fmaxf(dt, 0.0f), 50.0f);
        float decay = expf(-dt * (1.0f / TAU));
        atomicAdd(&delta[(long)nb * MM + m], decay * p);
    }
}

// ----------------- final dot + sigmoid -----------------
__global__ void score_kernel(float* __restrict__ out)
{
    int gw = (blockIdx.x * blockDim.x + threadIdx.x) >> 5;
    int lane = threadIdx.x & 31;
    if (gw >= E2) return;
    int e = (gw < EE) ? gw : (gw - EE);
    const float* u = g_proj + (long)e * DM;
    const float* v = g_proj + (long)((gw < EE) ? (EE + e) : (E2 + e)) * DM;
    float s = 0.0f;
    for (int c = lane; c < DM; c += 32) s += u[c] * v[c];
    #pragma unroll
    for (int off = 16; off > 0; off >>= 1) s += __shfl_down_sync(0xffffffffu, s, off);
    if (lane == 0) out[gw] = 1.0f / (1.0f + expf(-s));
}

// ----------------- launch -----------------
extern "C" void kernel_launch(void* const* d_in, const int* in_sizes, int n_in,
                              void* d_out, int out_size)
{
    const float* mem_s   = (const float*)d_in[0];
    const float* mem_g   = (const float*)d_in[1];
    const float* lu_s    = (const float*)d_in[2];
    const float* lu_g    = (const float*)d_in[3];
    const float* efeats  = (const float*)d_in[4];
    const float* etimes  = (const float*)d_in[5];
    const int*   src     = (const int*)d_in[6];
    const int*   dst     = (const int*)d_in[7];
    const int*   neg     = (const int*)d_in[8];
    const int*   eidx    = (const int*)d_in[9];
    const int*   nbrs    = (const int*)d_in[10];
    const float* W_merge = (const float*)d_in[11];
    const float* b_merge = (const float*)d_in[12];
    const float* W_msg   = (const float*)d_in[13];
    const float* b_msg   = (const float*)d_in[14];
    const float* Wx_s    = (const float*)d_in[15];
    const float* Wh_s    = (const float*)d_in[16];
    const float* bg_s    = (const float*)d_in[17];
    const float* Wx_g    = (const float*)d_in[18];
    const float* Wh_g    = (const float*)d_in[19];
    const float* bg_g    = (const float*)d_in[20];
    const float* Wp_s    = (const float*)d_in[21];
    const float* Wp_g    = (const float*)d_in[22];
    const float* W_s     = (const float*)d_in[23];
    const float* W_g     = (const float*)d_in[24];
    float* out = (float*)d_out;

    float *pMerged12, *pMsgs, *pGh, *pGxp, *pA3, *pMerged3, *pProj, *pW, *pWxp, *pBxp;
    cudaGetSymbolAddress((void**)&pMerged12, g_merged12);
    cudaGetSymbolAddress((void**)&pMsgs,     g_msgs);
    cudaGetSymbolAddress((void**)&pGh,       g_gh);
    cudaGetSymbolAddress((void**)&pGxp,      g_gxp);
    cudaGetSymbolAddress((void**)&pA3,       g_A3);
    cudaGetSymbolAddress((void**)&pMerged3,  g_merged3);
    cudaGetSymbolAddress((void**)&pProj,     g_proj);
    cudaGetSymbolAddress((void**)&pW,        g_wcvt);
    cudaGetSymbolAddress((void**)&pWxp,      g_wxp);
    cudaGetSymbolAddress((void**)&pBxp,      g_bxp);

    cudaFuncSetAttribute(gemm_tc<0,false>,  cudaFuncAttributeMaxDynamicSharedMemorySize, SMEM_BYTES);
    cudaFuncSetAttribute(gemm_tc<3,false>,  cudaFuncAttributeMaxDynamicSharedMemorySize, SMEM_BYTES);
    cudaFuncSetAttribute(gemm_pair_kernel,  cudaFuncAttributeMaxDynamicSharedMemorySize, SMEM_BYTES);

    const int BIG = 1 << 30;
    const float* cWm   = pW + OFF_WMERGE;
    const float* cWmsg = pW + OFF_WMSG;
    const float* cWhs  = pW + OFF_WHS;
    const float* cWhg  = pW + OFF_WHG;
    const float* cWs   = pW + OFF_WS;
    const float* cWg   = pW + OFF_WG;

    // L1: zero/flag + weight/ef conversions (all mutually independent, no smem)
    combo0_kernel<<<NB_Z + NB_W + NB_XP + NB_EF, 256>>>(
        W_merge, W_msg, Wh_s, Wh_g, W_s, W_g,
        Wx_s, Wp_s, Wx_g, Wp_g, bg_s, bg_g, efeats, eidx, src, dst, neg);

    // L2: last-occurrence (needs the -1 init from L1 first)
    last_occ_kernel<<<(EE + 255) / 256, 256>>>(src, dst);

    // L3: merge12 + gh fused (both independent GEMMs, same footprint)
    GemmP Pm12 = { nullptr, 0, 400, mem_s, mem_g, src, dst,
                   cWm, cWm, b_merge, b_merge, BIG, pMerged12, MM, 1, 1 };
    GemmP Pgh  = { nullptr, 0, 200, mem_s, mem_g, src, dst,
                   cWhs, cWhg, nullptr, nullptr, EE, pGh, 600, 0, 0 };
    gemm_pair_kernel<<<G1 + G2, 256, SMEM_BYTES>>>(Pm12, Pgh);

    // L4: msgs = round(relu(concat @ Wmsg + b))   [E2 x 572]x[572 x 100]
    GemmP Pmsg = { pMerged12, 0, 572, nullptr, nullptr, nullptr, nullptr,
                   cWmsg, cWmsg, b_msg, b_msg, BIG, pMsgs, DM, 2, 1 };
    gemm_tc<3,false><<<dim3(2, E2/128), 256, SMEM_BYTES>>>(Pmsg);

    // L5: gxp = msgs @ [Wx|Wp] + [bg|0]; tanh cols>=600   [E2 x 100]x[100 x 800]
    GemmP Pgxp = { pMsgs, DM, DM, nullptr, nullptr, nullptr, nullptr,
                   pWxp, pWxp + 80000, pBxp, pBxp + 800, EE, pGxp, 800, 3, 0 };
    gemm_tc<0,false><<<dim3(13, E2/128), 256, SMEM_BYTES>>>(Pgxp);

    // L6: GRU elementwise + scatter (dead scatters skipped via g_flag)
    gru_scatter_kernel<<<E2, 256>>>(mem_s, mem_g, src, dst, nbrs, etimes, lu_s, lu_g);

    // L7: A3 = round(mem+delta)
    prep_A3_kernel<<<E3/8, 256>>>(mem_s, mem_g, src, dst, neg);

    // L8: merged3 = round(tanh(A3 @ Wm + b))   [E3 x 400]x[400 x 200]
    GemmP Pm3 = { pA3, 400, 400, nullptr, nullptr, nullptr, nullptr,
                  cWm, cWm, b_merge, b_merge, BIG, pMerged3, MM, 1, 1 };
    gemm_tc<0,false><<<dim3(4, E3/128), 256, SMEM_BYTES>>>(Pm3);

    // L9: proj = merged3 @ (W_s | W_g)   [E3 x 200]x[200 x 100]
    GemmP Ppr = { pMerged3, MM, MM, nullptr, nullptr, nullptr, nullptr,
                  cWs, cWg, nullptr, nullptr, EE, pProj, DM, 0, 0 };
    gemm_tc<0,false><<<dim3(2, E3/128), 256, SMEM_BYTES>>>(Ppr);

    // L10: score
    score_kernel<<<(E2 * 32 + 255) / 256, 256>>>(out);
}